// round 7
// baseline (speedup 1.0000x reference)
#include <cuda_runtime.h>
#include <cuda_fp16.h>
#include <math.h>
#include <stdint.h>

// Problem constants (fixed by reference setup_inputs)
#define CB 4
#define CL 2048
#define CD 256
#define CH 8
#define CDK 32
#define CF 1024

// ---------------------------------------------------------------------------
// Scratch (device globals: allocation-free per harness rules)
// ---------------------------------------------------------------------------
__device__ __align__(16) float  g_m[CL * CDK];                   // 256 KB
__device__ __align__(16) __half g_P[(size_t)CL * CL];            // 8 MB : exp(scores), half
__device__ __align__(16) float  g_invden[CB * CL];               // 32 KB
__device__ __align__(16) float  g_T[(size_t)CB * CL * CD];       // 8 MB
__device__ __align__(16) float  g_Hn[(size_t)CB * CL * CD];      // 8 MB
__device__ __align__(16) __half g_Hnh[(size_t)CB * CL * CD];     // 4 MB
__device__ __align__(16) __half g_H1h[(size_t)CB * CL * CF];     // 16 MB
__device__ __align__(16) float  g_Y[(size_t)CB * CL * CD];       // 8 MB

// ---------------------------------------------------------------------------
// m[l, d] = mean over (b, h) of x[b, l, h*32 + d]
// ---------------------------------------------------------------------------
__global__ void k_mean(const float* __restrict__ x) {
    int idx = blockIdx.x * blockDim.x + threadIdx.x;
    if (idx >= CL * CDK) return;
    int l = idx / CDK;
    int d = idx % CDK;
    float s = 0.f;
#pragma unroll
    for (int b = 0; b < CB; b++)
#pragma unroll
        for (int h = 0; h < CH; h++)
            s += x[((size_t)(b * CL) + l) * CD + h * CDK + d];
    g_m[idx] = s * (1.f / 32.f);
}

// ---------------------------------------------------------------------------
// P[i, j] = half( exp( sin(clip(m_i . m_j, -pi, pi) * 0.5)^2 ) )
// ---------------------------------------------------------------------------
__global__ void k_scores() {
    __shared__ float mi[16][33];
    __shared__ float mj[16][33];
    int i0 = blockIdx.y * 16;
    int j0 = blockIdx.x * 16;
    int tx = threadIdx.x, ty = threadIdx.y;
    int t = ty * 16 + tx;
    for (int v = t; v < 16 * 32; v += 256) {
        int r = v >> 5, c = v & 31;
        mi[r][c] = g_m[(i0 + r) * CDK + c];
        mj[r][c] = g_m[(j0 + r) * CDK + c];
    }
    __syncthreads();
    float dot = 0.f;
#pragma unroll
    for (int k = 0; k < 32; k++) dot = fmaf(mi[ty][k], mj[tx][k], dot);
    const float PI = 3.14159265358979323846f;
    float ang = fminf(fmaxf(dot, -PI), PI);
    float s = sinf(ang * 0.5f);
    g_P[(size_t)(i0 + ty) * CL + (j0 + tx)] = __float2half_rn(expf(s * s));
}

// ---------------------------------------------------------------------------
// invden[b][i] = 1 / sum_j P[i,j] * (mask[b][j] != 0)   (P already half)
// ---------------------------------------------------------------------------
__global__ void k_denom(const int* __restrict__ mask) {
    __shared__ float red[CB][8];
    int i = blockIdx.x;
    int tid = threadIdx.x;  // 256
    const __half* Prow = g_P + (size_t)i * CL;
    float acc[CB] = {0.f, 0.f, 0.f, 0.f};
    for (int j = tid; j < CL; j += 256) {
        float p = __half2float(Prow[j]);
#pragma unroll
        for (int b = 0; b < CB; b++)
            acc[b] += (mask[b * CL + j] != 0) ? p : 0.f;
    }
#pragma unroll
    for (int b = 0; b < CB; b++) {
        float v = acc[b];
        for (int o = 16; o > 0; o >>= 1) v += __shfl_xor_sync(0xffffffffu, v, o);
        if ((tid & 31) == 0) red[b][tid >> 5] = v;
    }
    __syncthreads();
    if (tid < CB) {
        float s = 0.f;
#pragma unroll
        for (int w = 0; w < 8; w++) s += red[tid][w];
        g_invden[tid * CL + i] = 1.f / s;
    }
}

// ---------------------------------------------------------------------------
// FP16 mma.sync helpers
// ---------------------------------------------------------------------------
__device__ __forceinline__ uint32_t packh2(float lo, float hi) {
    __half2 h = __floats2half2_rn(lo, hi);
    return *(uint32_t*)&h;
}
__device__ __forceinline__ void mma16816(float* d, const uint4& a, const uint2& b) {
    asm volatile(
        "mma.sync.aligned.m16n8k16.row.col.f32.f16.f16.f32 "
        "{%0,%1,%2,%3}, {%4,%5,%6,%7}, {%8,%9}, {%0,%1,%2,%3};"
        : "+f"(d[0]), "+f"(d[1]), "+f"(d[2]), "+f"(d[3])
        : "r"(a.x), "r"(a.y), "r"(a.z), "r"(a.w), "r"(b.x), "r"(b.y));
}

// ---------------------------------------------------------------------------
// FP16 tensor-core GEMM: C[M,N] = A[M,K] @ B[K,N]
//   A: half, K-major (row stride = K)  — loaded as ready-made k-pairs
//   B: float, native [K][N] row-major — converted + paired at load
// CTA tile 128x128, BK=16, 8 warps (2x4), warp tile 64x32 via m16n8k16.
// SMEM tiles stored in MMA fragment layout (scattered at STS time).
// OPT bits: 1=+bias, 2=relu, 4=+residual(f32), 8=row-scale, 16=mask B rows,
//           32=emit half C (Ch) instead of float C
// ---------------------------------------------------------------------------
template <int OPT>
__global__ void __launch_bounds__(256) k_hgemm(
    const __half* __restrict__ A, const float* __restrict__ B,
    const int* __restrict__ maskB,
    const float* __restrict__ bias, const float* __restrict__ Res,
    const float* __restrict__ rscale,
    float* __restrict__ C, __half* __restrict__ Ch,
    int N, int K,
    size_t sB, size_t sR, size_t sS, size_t sC)
{
    __shared__ __align__(16) uint32_t As[2][1024];
    __shared__ __align__(16) uint32_t Bs[2][1024];

    const int tid = threadIdx.x;
    const int lane = tid & 31;
    const int wid = tid >> 5;
    const int wr = wid >> 2;       // warp row (0..1) -> 64 rows
    const int wc = wid & 3;        // warp col (0..3) -> 32 cols

    B += (size_t)blockIdx.z * sB;
    if (OPT & 4) Res += (size_t)blockIdx.z * sR;
    if (OPT & 8) rscale += (size_t)blockIdx.z * sS;
    if (OPT & 16) maskB += blockIdx.z * CL;
    const size_t czoff = (size_t)blockIdx.z * sC;

    const int m0 = blockIdx.y * 128;
    const int n0 = blockIdx.x * 128;

    // ---- A loader: thread -> (row, k-half). 1 x LDG.128 = 8 halves = 4 pairs.
    const int ar = tid >> 1;       // 0..127
    const int ah = tid & 1;        // 0 -> k 0..7, 1 -> k 8..15
    const __half* aptr = A + (size_t)(m0 + ar) * K + ah * 8;
    int aoff[4];
    {
        int rr = ar & 15, mf = (ar >> 4) & 3, wrr = ar >> 6;
        int w = (rr >> 3) + 2 * ah;
        int blk = (wrr * 4 + mf) * 32;
#pragma unroll
        for (int j = 0; j < 4; j++)
            aoff[j] = (blk + (rr & 7) * 4 + j) * 4 + w;
    }
    // ---- B loader: thread -> (k-pair kp, n-quad nq). 2 x LDG.128 rows.
    const int nq = tid >> 3;       // 0..31
    const int kp = tid & 7;        // 0..7
    const float* bptr0 = B + (size_t)(kp * 2) * N + n0 + nq * 4;
    const float* bptr1 = bptr0 + N;
    int boff[4];
#pragma unroll
    for (int i = 0; i < 4; i++) {
        int r = nq * 4 + i;
        int blk = ((r >> 5) * 4 + ((r & 31) >> 3)) * 32;
        boff[i] = (blk + (r & 7) * 4 + (kp & 3)) * 2 + (kp >> 2);
    }

    float acc[4][4][4];
#pragma unroll
    for (int i = 0; i < 4; i++)
#pragma unroll
        for (int j = 0; j < 4; j++)
#pragma unroll
            for (int q = 0; q < 4; q++) acc[i][j][q] = 0.f;

    const int NC = K >> 4;
    uint4 pa;
    float4 pb0, pb1;

    // prologue: chunk 0
    pa  = *(const uint4*)aptr;
    pb0 = *(const float4*)bptr0;
    pb1 = *(const float4*)bptr1;
    if (OPT & 16) {
        if (maskB[kp * 2]     == 0) pb0 = make_float4(0.f, 0.f, 0.f, 0.f);
        if (maskB[kp * 2 + 1] == 0) pb1 = make_float4(0.f, 0.f, 0.f, 0.f);
    }
    As[0][aoff[0]] = pa.x; As[0][aoff[1]] = pa.y;
    As[0][aoff[2]] = pa.z; As[0][aoff[3]] = pa.w;
    Bs[0][boff[0]] = packh2(pb0.x, pb1.x);
    Bs[0][boff[1]] = packh2(pb0.y, pb1.y);
    Bs[0][boff[2]] = packh2(pb0.z, pb1.z);
    Bs[0][boff[3]] = packh2(pb0.w, pb1.w);
    __syncthreads();

    for (int c = 0; c < NC; c++) {
        const int buf = c & 1;
        if (c + 1 < NC) {
            const int k0 = (c + 1) << 4;
            pa  = *(const uint4*)(aptr + k0);
            pb0 = *(const float4*)(bptr0 + (size_t)k0 * N);
            pb1 = *(const float4*)(bptr1 + (size_t)k0 * N);
            if (OPT & 16) {
                if (maskB[k0 + kp * 2]     == 0) pb0 = make_float4(0.f, 0.f, 0.f, 0.f);
                if (maskB[k0 + kp * 2 + 1] == 0) pb1 = make_float4(0.f, 0.f, 0.f, 0.f);
            }
        }
        uint4 af[4];
        uint2 bf[4];
#pragma unroll
        for (int i = 0; i < 4; i++)
            af[i] = *(const uint4*)&As[buf][((wr * 4 + i) * 32 + lane) * 4];
#pragma unroll
        for (int j = 0; j < 4; j++)
            bf[j] = *(const uint2*)&Bs[buf][((wc * 4 + j) * 32 + lane) * 2];
#pragma unroll
        for (int i = 0; i < 4; i++)
#pragma unroll
            for (int j = 0; j < 4; j++)
                mma16816(acc[i][j], af[i], bf[j]);
        if (c + 1 < NC) {
            const int nb = buf ^ 1;
            As[nb][aoff[0]] = pa.x; As[nb][aoff[1]] = pa.y;
            As[nb][aoff[2]] = pa.z; As[nb][aoff[3]] = pa.w;
            Bs[nb][boff[0]] = packh2(pb0.x, pb1.x);
            Bs[nb][boff[1]] = packh2(pb0.y, pb1.y);
            Bs[nb][boff[2]] = packh2(pb0.z, pb1.z);
            Bs[nb][boff[3]] = packh2(pb0.w, pb1.w);
        }
        __syncthreads();
    }

    // ---- epilogue ----
    const int rbase = m0 + wr * 64;
    const int cbase = n0 + wc * 32;
#pragma unroll
    for (int i = 0; i < 4; i++) {
        int row_lo = rbase + i * 16 + (lane >> 2);
        int row_hi = row_lo + 8;
        float rs_lo = 1.f, rs_hi = 1.f;
        if (OPT & 8) { rs_lo = rscale[row_lo]; rs_hi = rscale[row_hi]; }
#pragma unroll
        for (int j = 0; j < 4; j++) {
            int col = cbase + j * 8 + (lane & 3) * 2;
            float2 lo = make_float2(acc[i][j][0], acc[i][j][1]);
            float2 hi = make_float2(acc[i][j][2], acc[i][j][3]);
            if (OPT & 8) {
                lo.x *= rs_lo; lo.y *= rs_lo;
                hi.x *= rs_hi; hi.y *= rs_hi;
            }
            if (OPT & 1) {
                float2 bb = *(const float2*)&bias[col];
                lo.x += bb.x; lo.y += bb.y;
                hi.x += bb.x; hi.y += bb.y;
            }
            if (OPT & 2) {
                lo.x = fmaxf(lo.x, 0.f); lo.y = fmaxf(lo.y, 0.f);
                hi.x = fmaxf(hi.x, 0.f); hi.y = fmaxf(hi.y, 0.f);
            }
            if (OPT & 4) {
                float2 r0 = *(const float2*)&Res[(size_t)row_lo * N + col];
                float2 r1 = *(const float2*)&Res[(size_t)row_hi * N + col];
                lo.x += r0.x; lo.y += r0.y;
                hi.x += r1.x; hi.y += r1.y;
            }
            if (OPT & 32) {
                *(uint32_t*)&Ch[czoff + (size_t)row_lo * N + col] = packh2(lo.x, lo.y);
                *(uint32_t*)&Ch[czoff + (size_t)row_hi * N + col] = packh2(hi.x, hi.y);
            } else {
                *(float2*)&C[czoff + (size_t)row_lo * N + col] = lo;
                *(float2*)&C[czoff + (size_t)row_hi * N + col] = hi;
            }
        }
    }
}

// ---------------------------------------------------------------------------
// LayerNorm over last dim D=256; optional extra half output
// ---------------------------------------------------------------------------
__global__ void k_ln(const float* __restrict__ in, const float* __restrict__ gw,
                     const float* __restrict__ bw, float* __restrict__ out,
                     __half* __restrict__ outh) {
    __shared__ float red[8];
    int row = blockIdx.x;
    int tid = threadIdx.x;
    float v = in[(size_t)row * CD + tid];

    float s = v;
    for (int o = 16; o > 0; o >>= 1) s += __shfl_xor_sync(0xffffffffu, s, o);
    if ((tid & 31) == 0) red[tid >> 5] = s;
    __syncthreads();
    if (tid < 32) {
        float r = (tid < 8) ? red[tid] : 0.f;
        for (int o = 4; o > 0; o >>= 1) r += __shfl_xor_sync(0xffffffffu, r, o);
        if (tid == 0) red[0] = r;
    }
    __syncthreads();
    float mu = red[0] * (1.f / CD);
    __syncthreads();

    float t = v - mu;
    float s2 = t * t;
    for (int o = 16; o > 0; o >>= 1) s2 += __shfl_xor_sync(0xffffffffu, s2, o);
    if ((tid & 31) == 0) red[tid >> 5] = s2;
    __syncthreads();
    if (tid < 32) {
        float r = (tid < 8) ? red[tid] : 0.f;
        for (int o = 4; o > 0; o >>= 1) r += __shfl_xor_sync(0xffffffffu, r, o);
        if (tid == 0) red[0] = r;
    }
    __syncthreads();
    float var = red[0] * (1.f / CD);
    float y = t * rsqrtf(var + 1e-5f) * gw[tid] + bw[tid];
    out[(size_t)row * CD + tid] = y;
    if (outh) outh[(size_t)row * CD + tid] = __float2half_rn(y);
}

// ---------------------------------------------------------------------------
// kernel_launch
// ---------------------------------------------------------------------------
extern "C" void kernel_launch(void* const* d_in, const int* in_sizes, int n_in,
                              void* d_out, int out_size) {
    const float* x    = (const float*)d_in[0];
    const int*   mask = (const int*)  d_in[1];
    const float* W1   = (const float*)d_in[2];
    const float* b1   = (const float*)d_in[3];
    const float* W2   = (const float*)d_in[4];
    const float* b2   = (const float*)d_in[5];
    const float* g1   = (const float*)d_in[6];
    const float* be1  = (const float*)d_in[7];
    const float* g2   = (const float*)d_in[8];
    const float* be2  = (const float*)d_in[9];
    float* out = (float*)d_out;

    __half *pP, *pHnh, *pH1h;
    float *pInv, *pT, *pHn, *pY;
    cudaGetSymbolAddress((void**)&pP,   g_P);
    cudaGetSymbolAddress((void**)&pInv, g_invden);
    cudaGetSymbolAddress((void**)&pT,   g_T);
    cudaGetSymbolAddress((void**)&pHn,  g_Hn);
    cudaGetSymbolAddress((void**)&pHnh, g_Hnh);
    cudaGetSymbolAddress((void**)&pH1h, g_H1h);
    cudaGetSymbolAddress((void**)&pY,   g_Y);

    // 1) token mean
    k_mean<<<(CL * CDK + 255) / 256, 256>>>(x);
    // 2) P = half(exp(scores))
    k_scores<<<dim3(CL / 16, CL / 16), dim3(16, 16)>>>();
    // 3) per-batch softmax denominators
    k_denom<<<CL, 256>>>(mask);

    // 4) T_b = (P @ (mask_b . x_b)) * invden_b + x_b   [attn_out + residual]
    //    OPT = 16(mask) | 8(rscale) | 4(residual)
    k_hgemm<28><<<dim3(CD / 128, CL / 128, CB), 256>>>(
        pP, x, mask, nullptr, x, pInv, pT, nullptr,
        CD, CL,
        (size_t)CL * CD, (size_t)CL * CD, (size_t)CL, (size_t)CL * CD);

    // 5) Hn = LN(T, g1, be1)  (+ half copy for GEMM2 A)
    k_ln<<<CB * CL, CD>>>(pT, g1, be1, pHn, pHnh);

    // 6) H1h = half(relu(Hn @ W1 + b1))   OPT = 1|2|32
    k_hgemm<35><<<dim3(CF / 128, (CB * CL) / 128, 1), 256>>>(
        pHnh, W1, nullptr, b1, nullptr, nullptr, nullptr, pH1h,
        CF, CD, 0, 0, 0, 0);

    // 7) Y = Hn + H1 @ W2 + b2            OPT = 1|4
    k_hgemm<5><<<dim3(CD / 128, (CB * CL) / 128, 1), 256>>>(
        pH1h, W2, nullptr, b2, pHn, nullptr, pY, nullptr,
        CD, CF, 0, 0, 0, 0);

    // 8) out = LN(Y, g2, be2)
    k_ln<<<CB * CL, CD>>>(pY, g2, be2, out, nullptr);
}

// round 8
// speedup vs baseline: 1.6478x; 1.6478x over previous
#include <cuda_runtime.h>
#include <cuda_fp16.h>
#include <math.h>
#include <stdint.h>

// Problem constants (fixed by reference setup_inputs)
#define CB 4
#define CL 2048
#define CD 256
#define CH 8
#define CDK 32
#define CF 1024

// ---------------------------------------------------------------------------
// Scratch (device globals: allocation-free per harness rules)
// ---------------------------------------------------------------------------
__device__ __align__(16) float  g_m[CL * CDK];                   // 256 KB
__device__ __align__(16) __half g_P[(size_t)CL * CL];            // 8 MB : exp(scores)
__device__ __align__(16) float  g_invden[CB * CL];               // 32 KB
__device__ __align__(16) float  g_part[(size_t)16 * CL * CD];    // 32 MB: split-K partials
__device__ __align__(16) float  g_Hn[(size_t)CB * CL * CD];      // 8 MB
__device__ __align__(16) __half g_Hnh[(size_t)CB * CL * CD];     // 4 MB
__device__ __align__(16) __half g_H1h[(size_t)CB * CL * CF];     // 16 MB

// ---------------------------------------------------------------------------
// m[l, d] = mean over (b, h) of x[b, l, h*32 + d]
// ---------------------------------------------------------------------------
__global__ void k_mean(const float* __restrict__ x) {
    int idx = blockIdx.x * blockDim.x + threadIdx.x;
    if (idx >= CL * CDK) return;
    int l = idx / CDK;
    int d = idx % CDK;
    float s = 0.f;
#pragma unroll
    for (int b = 0; b < CB; b++)
#pragma unroll
        for (int h = 0; h < CH; h++)
            s += x[((size_t)(b * CL) + l) * CD + h * CDK + d];
    g_m[idx] = s * (1.f / 32.f);
}

// ---------------------------------------------------------------------------
// P[i, j] = half( exp( sin(clip(m_i . m_j, -pi, pi) * 0.5)^2 ) )
// ---------------------------------------------------------------------------
__global__ void k_scores() {
    __shared__ float mi[16][33];
    __shared__ float mj[16][33];
    int i0 = blockIdx.y * 16;
    int j0 = blockIdx.x * 16;
    int tx = threadIdx.x, ty = threadIdx.y;
    int t = ty * 16 + tx;
    for (int v = t; v < 16 * 32; v += 256) {
        int r = v >> 5, c = v & 31;
        mi[r][c] = g_m[(i0 + r) * CDK + c];
        mj[r][c] = g_m[(j0 + r) * CDK + c];
    }
    __syncthreads();
    float dot = 0.f;
#pragma unroll
    for (int k = 0; k < 32; k++) dot = fmaf(mi[ty][k], mj[tx][k], dot);
    const float PI = 3.14159265358979323846f;
    float ang = fminf(fmaxf(dot, -PI), PI);
    float s = sinf(ang * 0.5f);
    g_P[(size_t)(i0 + ty) * CL + (j0 + tx)] = __float2half_rn(expf(s * s));
}

// ---------------------------------------------------------------------------
// invden[b][i] = 1 / sum_j P[i,j] * (mask[b][j] != 0)
// ---------------------------------------------------------------------------
__global__ void k_denom(const int* __restrict__ mask) {
    __shared__ float red[CB][8];
    int i = blockIdx.x;
    int tid = threadIdx.x;  // 256
    const __half* Prow = g_P + (size_t)i * CL;
    float acc[CB] = {0.f, 0.f, 0.f, 0.f};
    for (int j = tid; j < CL; j += 256) {
        float p = __half2float(Prow[j]);
#pragma unroll
        for (int b = 0; b < CB; b++)
            acc[b] += (mask[b * CL + j] != 0) ? p : 0.f;
    }
#pragma unroll
    for (int b = 0; b < CB; b++) {
        float v = acc[b];
        for (int o = 16; o > 0; o >>= 1) v += __shfl_xor_sync(0xffffffffu, v, o);
        if ((tid & 31) == 0) red[b][tid >> 5] = v;
    }
    __syncthreads();
    if (tid < CB) {
        float s = 0.f;
#pragma unroll
        for (int w = 0; w < 8; w++) s += red[tid][w];
        g_invden[tid * CL + i] = 1.f / s;
    }
}

// ---------------------------------------------------------------------------
// FP16 mma.sync helpers
// ---------------------------------------------------------------------------
__device__ __forceinline__ uint32_t packh2(float lo, float hi) {
    __half2 h = __floats2half2_rn(lo, hi);
    return *(uint32_t*)&h;
}
__device__ __forceinline__ void mma16816(float* d, const uint4& a, const uint2& b) {
    asm volatile(
        "mma.sync.aligned.m16n8k16.row.col.f32.f16.f16.f32 "
        "{%0,%1,%2,%3}, {%4,%5,%6,%7}, {%8,%9}, {%0,%1,%2,%3};"
        : "+f"(d[0]), "+f"(d[1]), "+f"(d[2]), "+f"(d[3])
        : "r"(a.x), "r"(a.y), "r"(a.z), "r"(a.w), "r"(b.x), "r"(b.y));
}

// ---------------------------------------------------------------------------
// FP16 tensor-core GEMM: C[M,N] = A[M,K] @ B[K,N]   (K split SPLIT ways)
//   A: half, K-major (row stride = K full)
//   B: float, native [K][N] row-major — converted + paired at load
// CTA tile 128x128, BK=16, 8 warps (2x4), warp tile 64x32 via m16n8k16.
// blockIdx.z = b * SPLIT + s. Raw path (OPT&64) writes fp32 partial tile.
// OPT bits: 1=+bias, 2=relu, 16=mask B rows, 32=half C out, 64=raw partial
// ---------------------------------------------------------------------------
template <int OPT, int SPLIT>
__global__ void __launch_bounds__(256, 2) k_hgemm(
    const __half* __restrict__ A, const float* __restrict__ B,
    const int* __restrict__ maskB, const float* __restrict__ bias,
    float* __restrict__ C, __half* __restrict__ Ch,
    int N, int K,
    size_t sB, size_t sC)
{
    __shared__ __align__(16) uint32_t As[2][1024];
    __shared__ __align__(16) uint32_t Bs[2][1024];

    const int tid = threadIdx.x;
    const int lane = tid & 31;
    const int wid = tid >> 5;
    const int wr = wid >> 2;       // warp row (0..1) -> 64 rows
    const int wc = wid & 3;        // warp col (0..3) -> 32 cols

    const int z = blockIdx.z;
    const int bb = z / SPLIT;      // batch
    const int sp = z % SPLIT;      // K split index
    const int kt = K / SPLIT;      // K per split
    const int ksta = sp * kt;

    B += (size_t)bb * sB + (size_t)ksta * N;
    if (OPT & 16) maskB += bb * CL + ksta;
    const size_t czoff = (size_t)z * sC;   // raw: per-z stride; else per-batch

    const int m0 = blockIdx.y * 128;
    const int n0 = blockIdx.x * 128;

    // ---- A loader: thread -> (row, k-half). 1 x LDG.128 = 8 halves.
    const int ar = tid >> 1;
    const int ah = tid & 1;
    const __half* aptr = A + (size_t)(m0 + ar) * K + ksta + ah * 8;
    int aoff[4];
    {
        int rr = ar & 15, mf = (ar >> 4) & 3, wrr = ar >> 6;
        int w = (rr >> 3) + 2 * ah;
        int blk = (wrr * 4 + mf) * 32;
#pragma unroll
        for (int j = 0; j < 4; j++)
            aoff[j] = (blk + (rr & 7) * 4 + j) * 4 + w;
    }
    // ---- B loader: thread -> (k-pair kp, n-quad nq).
    const int nq = tid >> 3;
    const int kp = tid & 7;
    const float* bptr0 = B + (size_t)(kp * 2) * N + n0 + nq * 4;
    const float* bptr1 = bptr0 + N;
    int boff[4];
#pragma unroll
    for (int i = 0; i < 4; i++) {
        int r = nq * 4 + i;
        int blk = ((r >> 5) * 4 + ((r & 31) >> 3)) * 32;
        boff[i] = (blk + (r & 7) * 4 + (kp & 3)) * 2 + (kp >> 2);
    }

    float acc[4][4][4];
#pragma unroll
    for (int i = 0; i < 4; i++)
#pragma unroll
        for (int j = 0; j < 4; j++)
#pragma unroll
            for (int q = 0; q < 4; q++) acc[i][j][q] = 0.f;

    const int NC = kt >> 4;
    uint4 pa;
    float4 pb0, pb1;

    pa  = *(const uint4*)aptr;
    pb0 = *(const float4*)bptr0;
    pb1 = *(const float4*)bptr1;
    if (OPT & 16) {
        if (maskB[kp * 2]     == 0) pb0 = make_float4(0.f, 0.f, 0.f, 0.f);
        if (maskB[kp * 2 + 1] == 0) pb1 = make_float4(0.f, 0.f, 0.f, 0.f);
    }
    As[0][aoff[0]] = pa.x; As[0][aoff[1]] = pa.y;
    As[0][aoff[2]] = pa.z; As[0][aoff[3]] = pa.w;
    Bs[0][boff[0]] = packh2(pb0.x, pb1.x);
    Bs[0][boff[1]] = packh2(pb0.y, pb1.y);
    Bs[0][boff[2]] = packh2(pb0.z, pb1.z);
    Bs[0][boff[3]] = packh2(pb0.w, pb1.w);
    __syncthreads();

    for (int c = 0; c < NC; c++) {
        const int buf = c & 1;
        if (c + 1 < NC) {
            const int k0 = (c + 1) << 4;
            pa  = *(const uint4*)(aptr + k0);
            pb0 = *(const float4*)(bptr0 + (size_t)k0 * N);
            pb1 = *(const float4*)(bptr1 + (size_t)k0 * N);
            if (OPT & 16) {
                if (maskB[k0 + kp * 2]     == 0) pb0 = make_float4(0.f, 0.f, 0.f, 0.f);
                if (maskB[k0 + kp * 2 + 1] == 0) pb1 = make_float4(0.f, 0.f, 0.f, 0.f);
            }
        }
        uint4 af[4];
        uint2 bf[4];
#pragma unroll
        for (int i = 0; i < 4; i++)
            af[i] = *(const uint4*)&As[buf][((wr * 4 + i) * 32 + lane) * 4];
#pragma unroll
        for (int j = 0; j < 4; j++)
            bf[j] = *(const uint2*)&Bs[buf][((wc * 4 + j) * 32 + lane) * 2];
#pragma unroll
        for (int i = 0; i < 4; i++)
#pragma unroll
            for (int j = 0; j < 4; j++)
                mma16816(acc[i][j], af[i], bf[j]);
        if (c + 1 < NC) {
            const int nb = buf ^ 1;
            As[nb][aoff[0]] = pa.x; As[nb][aoff[1]] = pa.y;
            As[nb][aoff[2]] = pa.z; As[nb][aoff[3]] = pa.w;
            Bs[nb][boff[0]] = packh2(pb0.x, pb1.x);
            Bs[nb][boff[1]] = packh2(pb0.y, pb1.y);
            Bs[nb][boff[2]] = packh2(pb0.z, pb1.z);
            Bs[nb][boff[3]] = packh2(pb0.w, pb1.w);
        }
        __syncthreads();
    }

    // ---- epilogue ----
    const int rbase = m0 + wr * 64;
    const int cbase = n0 + wc * 32;
#pragma unroll
    for (int i = 0; i < 4; i++) {
        int row_lo = rbase + i * 16 + (lane >> 2);
        int row_hi = row_lo + 8;
#pragma unroll
        for (int j = 0; j < 4; j++) {
            int col = cbase + j * 8 + (lane & 3) * 2;
            float2 lo = make_float2(acc[i][j][0], acc[i][j][1]);
            float2 hi = make_float2(acc[i][j][2], acc[i][j][3]);
            if (OPT & 64) {   // raw partial out
                *(float2*)&C[czoff + (size_t)row_lo * N + col] = lo;
                *(float2*)&C[czoff + (size_t)row_hi * N + col] = hi;
                continue;
            }
            if (OPT & 1) {
                float2 bbv = *(const float2*)&bias[col];
                lo.x += bbv.x; lo.y += bbv.y;
                hi.x += bbv.x; hi.y += bbv.y;
            }
            if (OPT & 2) {
                lo.x = fmaxf(lo.x, 0.f); lo.y = fmaxf(lo.y, 0.f);
                hi.x = fmaxf(hi.x, 0.f); hi.y = fmaxf(hi.y, 0.f);
            }
            if (OPT & 32) {
                *(uint32_t*)&Ch[czoff + (size_t)row_lo * N + col] = packh2(lo.x, lo.y);
                *(uint32_t*)&Ch[czoff + (size_t)row_hi * N + col] = packh2(hi.x, hi.y);
            } else {
                *(float2*)&C[czoff + (size_t)row_lo * N + col] = lo;
                *(float2*)&C[czoff + (size_t)row_hi * N + col] = hi;
            }
        }
    }
}

// ---------------------------------------------------------------------------
// Reduce 4 split-K partials + rscale + residual(x) -> LN -> Hn (f32 + half)
// One block (256 thr) per row. blockIdx.x = b*CL + m.
// ---------------------------------------------------------------------------
__global__ void k_red_ln1(const float* __restrict__ x,
                          const float* __restrict__ gw, const float* __restrict__ bw) {
    __shared__ float red[8];
    int r = blockIdx.x;            // 0..CB*CL-1
    int b = r >> 11;
    int m = r & (CL - 1);
    int tid = threadIdx.x;
    size_t rowoff = (size_t)m * CD + tid;
    size_t zstride = (size_t)CL * CD;

    float v = g_part[((size_t)(b * 4 + 0)) * zstride + rowoff]
            + g_part[((size_t)(b * 4 + 1)) * zstride + rowoff]
            + g_part[((size_t)(b * 4 + 2)) * zstride + rowoff]
            + g_part[((size_t)(b * 4 + 3)) * zstride + rowoff];
    v = v * g_invden[b * CL + m] + x[(size_t)r * CD + tid];

    float s = v;
    for (int o = 16; o > 0; o >>= 1) s += __shfl_xor_sync(0xffffffffu, s, o);
    if ((tid & 31) == 0) red[tid >> 5] = s;
    __syncthreads();
    if (tid < 32) {
        float rr = (tid < 8) ? red[tid] : 0.f;
        for (int o = 4; o > 0; o >>= 1) rr += __shfl_xor_sync(0xffffffffu, rr, o);
        if (tid == 0) red[0] = rr;
    }
    __syncthreads();
    float mu = red[0] * (1.f / CD);
    __syncthreads();
    float t = v - mu;
    float s2 = t * t;
    for (int o = 16; o > 0; o >>= 1) s2 += __shfl_xor_sync(0xffffffffu, s2, o);
    if ((tid & 31) == 0) red[tid >> 5] = s2;
    __syncthreads();
    if (tid < 32) {
        float rr = (tid < 8) ? red[tid] : 0.f;
        for (int o = 4; o > 0; o >>= 1) rr += __shfl_xor_sync(0xffffffffu, rr, o);
        if (tid == 0) red[0] = rr;
    }
    __syncthreads();
    float var = red[0] * (1.f / CD);
    float y = t * rsqrtf(var + 1e-5f) * gw[tid] + bw[tid];
    g_Hn[(size_t)r * CD + tid] = y;
    g_Hnh[(size_t)r * CD + tid] = __float2half_rn(y);
}

// ---------------------------------------------------------------------------
// Reduce 4 split-K partials + bias + residual(Hn) -> LN -> out
// ---------------------------------------------------------------------------
__global__ void k_red_ln2(const float* __restrict__ b2,
                          const float* __restrict__ gw, const float* __restrict__ bw,
                          float* __restrict__ out) {
    __shared__ float red[8];
    int r = blockIdx.x;            // 0..CB*CL-1
    int tid = threadIdx.x;
    size_t rowoff = (size_t)r * CD + tid;
    size_t zstride = (size_t)CB * CL * CD;

    float v = g_part[0 * zstride + rowoff] + g_part[1 * zstride + rowoff]
            + g_part[2 * zstride + rowoff] + g_part[3 * zstride + rowoff];
    v += b2[tid] + g_Hn[rowoff];

    float s = v;
    for (int o = 16; o > 0; o >>= 1) s += __shfl_xor_sync(0xffffffffu, s, o);
    if ((tid & 31) == 0) red[tid >> 5] = s;
    __syncthreads();
    if (tid < 32) {
        float rr = (tid < 8) ? red[tid] : 0.f;
        for (int o = 4; o > 0; o >>= 1) rr += __shfl_xor_sync(0xffffffffu, rr, o);
        if (tid == 0) red[0] = rr;
    }
    __syncthreads();
    float mu = red[0] * (1.f / CD);
    __syncthreads();
    float t = v - mu;
    float s2 = t * t;
    for (int o = 16; o > 0; o >>= 1) s2 += __shfl_xor_sync(0xffffffffu, s2, o);
    if ((tid & 31) == 0) red[tid >> 5] = s2;
    __syncthreads();
    if (tid < 32) {
        float rr = (tid < 8) ? red[tid] : 0.f;
        for (int o = 4; o > 0; o >>= 1) rr += __shfl_xor_sync(0xffffffffu, rr, o);
        if (tid == 0) red[0] = rr;
    }
    __syncthreads();
    float var = red[0] * (1.f / CD);
    out[rowoff] = t * rsqrtf(var + 1e-5f) * gw[tid] + bw[tid];
}

// ---------------------------------------------------------------------------
// kernel_launch
// ---------------------------------------------------------------------------
extern "C" void kernel_launch(void* const* d_in, const int* in_sizes, int n_in,
                              void* d_out, int out_size) {
    const float* x    = (const float*)d_in[0];
    const int*   mask = (const int*)  d_in[1];
    const float* W1   = (const float*)d_in[2];
    const float* b1   = (const float*)d_in[3];
    const float* W2   = (const float*)d_in[4];
    const float* b2   = (const float*)d_in[5];
    const float* g1   = (const float*)d_in[6];
    const float* be1  = (const float*)d_in[7];
    const float* g2   = (const float*)d_in[8];
    const float* be2  = (const float*)d_in[9];
    float* out = (float*)d_out;

    __half *pP, *pHnh, *pH1h;
    float *pPart;
    cudaGetSymbolAddress((void**)&pP,    g_P);
    cudaGetSymbolAddress((void**)&pPart, g_part);
    cudaGetSymbolAddress((void**)&pHnh,  g_Hnh);
    cudaGetSymbolAddress((void**)&pH1h,  g_H1h);

    // 1) token mean
    k_mean<<<(CL * CDK + 255) / 256, 256>>>(x);
    // 2) P = half(exp(scores))
    k_scores<<<dim3(CL / 16, CL / 16), dim3(16, 16)>>>();
    // 3) per-batch softmax denominators
    k_denom<<<CL, 256>>>(mask);

    // 4) GEMM1 split-K4: part[b*4+s] = P[:, ks] @ (mask_b . x_b)[ks, :]
    //    OPT = 64(raw) | 16(mask), grid z = CB*4 = 16 -> 512 CTAs
    k_hgemm<80, 4><<<dim3(CD / 128, CL / 128, CB * 4), 256>>>(
        pP, x, mask, nullptr, pPart, nullptr,
        CD, CL,
        (size_t)CL * CD, (size_t)CL * CD);

    // 5) reduce + invden + residual(x) + LN1 -> Hn, Hnh
    k_red_ln1<<<CB * CL, CD>>>(x, g1, be1);

    // 6) H1h = half(relu(Hn @ W1 + b1))   OPT = 1|2|32, 512 CTAs
    k_hgemm<35, 1><<<dim3(CF / 128, (CB * CL) / 128, 1), 256>>>(
        pHnh, W1, nullptr, b1, nullptr, pH1h,
        CF, CD, 0, 0);

    // 7) GEMM3 split-K4: part[s] = H1h[:, ks] @ W2[ks, :]  (raw), 512 CTAs
    k_hgemm<64, 4><<<dim3(CD / 128, (CB * CL) / 128, 4), 256>>>(
        pH1h, W2, nullptr, nullptr, pPart, nullptr,
        CD, CF, 0, (size_t)CB * CL * CD);

    // 8) reduce + bias + residual(Hn) + LN2 -> out
    k_red_ln2<<<CB * CL, CD>>>(b2, g2, be2, out);
}

// round 11
// speedup vs baseline: 2.8183x; 1.7104x over previous
#include <cuda_runtime.h>
#include <cuda_fp16.h>
#include <math.h>
#include <stdint.h>

// Problem constants (fixed by reference setup_inputs)
#define CB 4
#define CL 2048
#define CD 256
#define CH 8
#define CDK 32
#define CF 1024

// ---------------------------------------------------------------------------
// Scratch (device globals: allocation-free per harness rules)
// ---------------------------------------------------------------------------
__device__ __align__(16) float  g_m[CL * CDK];                   // 256 KB
__device__ __align__(16) __half g_P[(size_t)CL * CL];            // 8 MB : exp(scores)
__device__ __align__(16) float  g_invden[CB * CL];               // 32 KB
__device__ __align__(16) float  g_part[(size_t)16 * CL * CD];    // 32 MB: split-K partials
__device__ __align__(16) float  g_Hn[(size_t)CB * CL * CD];      // 8 MB
__device__ __align__(16) __half g_Hnh[(size_t)CB * CL * CD];     // 4 MB
__device__ __align__(16) __half g_H1h[(size_t)CB * CL * CF];     // 16 MB
__device__ __align__(16) __half g_xh[(size_t)CB * CL * CD];      // 4 MB : masked x, half
__device__ __align__(16) __half g_W1h[(size_t)CD * CF];          // 512 KB
__device__ __align__(16) __half g_W2h[(size_t)CF * CD];          // 512 KB

// ---------------------------------------------------------------------------
// m[l, d] = mean over (b, h) of x[b, l, h*32 + d]
// ---------------------------------------------------------------------------
__global__ void k_mean(const float* __restrict__ x) {
    int idx = blockIdx.x * blockDim.x + threadIdx.x;
    if (idx >= CL * CDK) return;
    int l = idx / CDK;
    int d = idx % CDK;
    float s = 0.f;
#pragma unroll
    for (int b = 0; b < CB; b++)
#pragma unroll
        for (int h = 0; h < CH; h++)
            s += x[((size_t)(b * CL) + l) * CD + h * CDK + d];
    g_m[idx] = s * (1.f / 32.f);
}

// ---------------------------------------------------------------------------
// P[i, j] = half( exp( sin(clip(m_i . m_j, -pi, pi) * 0.5)^2 ) )
// ---------------------------------------------------------------------------
__global__ void k_scores() {
    __shared__ float mi[16][33];
    __shared__ float mj[16][33];
    int i0 = blockIdx.y * 16;
    int j0 = blockIdx.x * 16;
    int tx = threadIdx.x, ty = threadIdx.y;
    int t = ty * 16 + tx;
    for (int v = t; v < 16 * 32; v += 256) {
        int r = v >> 5, c = v & 31;
        mi[r][c] = g_m[(i0 + r) * CDK + c];
        mj[r][c] = g_m[(j0 + r) * CDK + c];
    }
    __syncthreads();
    float dot = 0.f;
#pragma unroll
    for (int k = 0; k < 32; k++) dot = fmaf(mi[ty][k], mj[tx][k], dot);
    const float PI = 3.14159265358979323846f;
    float ang = fminf(fmaxf(dot, -PI), PI);
    float s = sinf(ang * 0.5f);
    g_P[(size_t)(i0 + ty) * CL + (j0 + tx)] = __float2half_rn(expf(s * s));
}

// ---------------------------------------------------------------------------
// invden[b][i] = 1 / sum_j P[i,j] * (mask[b][j] != 0)
// ---------------------------------------------------------------------------
__global__ void k_denom(const int* __restrict__ mask) {
    __shared__ float red[CB][8];
    int i = blockIdx.x;
    int tid = threadIdx.x;  // 256
    const __half* Prow = g_P + (size_t)i * CL;
    float acc[CB] = {0.f, 0.f, 0.f, 0.f};
    for (int j = tid; j < CL; j += 256) {
        float p = __half2float(Prow[j]);
#pragma unroll
        for (int b = 0; b < CB; b++)
            acc[b] += (mask[b * CL + j] != 0) ? p : 0.f;
    }
#pragma unroll
    for (int b = 0; b < CB; b++) {
        float v = acc[b];
        for (int o = 16; o > 0; o >>= 1) v += __shfl_xor_sync(0xffffffffu, v, o);
        if ((tid & 31) == 0) red[b][tid >> 5] = v;
    }
    __syncthreads();
    if (tid < CB) {
        float s = 0.f;
#pragma unroll
        for (int w = 0; w < 8; w++) s += red[tid][w];
        g_invden[tid * CL + i] = 1.f / s;
    }
}

// ---------------------------------------------------------------------------
// Half conversions of B operands
// ---------------------------------------------------------------------------
__device__ __forceinline__ uint32_t packh2(float lo, float hi) {
    __half2 h = __floats2half2_rn(lo, hi);
    return *(uint32_t*)&h;
}

// xh[e] = half(mask[row] ? x[e] : 0), row = e / CD
__global__ void k_xh(const float* __restrict__ x, const int* __restrict__ mask) {
    int i4 = blockIdx.x * 256 + threadIdx.x;
    int e = i4 * 4;
    float4 v = *(const float4*)&x[e];
    if (mask[e >> 8] == 0) v = make_float4(0.f, 0.f, 0.f, 0.f);
    uint2 o;
    o.x = packh2(v.x, v.y);
    o.y = packh2(v.z, v.w);
    *(uint2*)&g_xh[e] = o;
}

// generic float -> half convert (n divisible by 1024)
__global__ void k_wh(const float* __restrict__ w, __half* __restrict__ out) {
    int i4 = blockIdx.x * 256 + threadIdx.x;
    int e = i4 * 4;
    float4 v = *(const float4*)&w[e];
    uint2 o;
    o.x = packh2(v.x, v.y);
    o.y = packh2(v.z, v.w);
    *(uint2*)&out[e] = o;
}

// ---------------------------------------------------------------------------
// mma / ldmatrix / cp.async helpers
// ---------------------------------------------------------------------------
__device__ __forceinline__ void mma16816(float* d, const uint4& a, const uint2& b) {
    asm volatile(
        "mma.sync.aligned.m16n8k16.row.col.f32.f16.f16.f32 "
        "{%0,%1,%2,%3}, {%4,%5,%6,%7}, {%8,%9}, {%0,%1,%2,%3};"
        : "+f"(d[0]), "+f"(d[1]), "+f"(d[2]), "+f"(d[3])
        : "r"(a.x), "r"(a.y), "r"(a.z), "r"(a.w), "r"(b.x), "r"(b.y));
}
__device__ __forceinline__ void ldsm4(uint4& d, uint32_t a) {
    asm volatile("ldmatrix.sync.aligned.m8n8.x4.shared.b16 {%0,%1,%2,%3}, [%4];"
        : "=r"(d.x), "=r"(d.y), "=r"(d.z), "=r"(d.w) : "r"(a));
}
__device__ __forceinline__ void ldsm4t(uint32_t& r0, uint32_t& r1,
                                       uint32_t& r2, uint32_t& r3, uint32_t a) {
    asm volatile("ldmatrix.sync.aligned.m8n8.x4.trans.shared.b16 {%0,%1,%2,%3}, [%4];"
        : "=r"(r0), "=r"(r1), "=r"(r2), "=r"(r3) : "r"(a));
}
__device__ __forceinline__ void cpasync16(uint32_t s, const void* g) {
    asm volatile("cp.async.cg.shared.global [%0], [%1], 16;" :: "r"(s), "l"(g));
}
#define CP_COMMIT() asm volatile("cp.async.commit_group;" ::: "memory")
#define CP_WAIT1()  asm volatile("cp.async.wait_group 1;" ::: "memory")

// ---------------------------------------------------------------------------
// FP16 tensor-core GEMM (cp.async 3-stage + ldmatrix):
//   C[M,N] = A[M,K] @ B[K,N], A half K-major, B half [K][N] row-major.
// CTA tile 128x128, BK=64, 8 warps (2x4), warp tile 64x32 via m16n8k16.
// SMEM per stage: A 128x(64h)=16KB swizzled, B 64x(128h)=16KB swizzled.
// blockIdx.z = b * SPLIT + s (split-K).
// OPT bits: 1=+bias, 2=relu, 32=half C out, 64=raw fp32 partial out
// ---------------------------------------------------------------------------
template <int OPT, int SPLIT>
__global__ void __launch_bounds__(256, 2) k_hgemm(
    const __half* __restrict__ A, const __half* __restrict__ B,
    const float* __restrict__ bias,
    float* __restrict__ C, __half* __restrict__ Ch,
    int N, int K, size_t sB, size_t sC)
{
    extern __shared__ __align__(128) char smem[];
    const int tid = threadIdx.x;
    const int lane = tid & 31;
    const int wid = tid >> 5;
    const int wr = wid >> 2;       // warp row (0..1) -> 64 rows
    const int wc = wid & 3;        // warp col (0..3) -> 32 cols

    const int z = blockIdx.z;
    const int bb = z / SPLIT;
    const int sp = z % SPLIT;
    const int kt = K / SPLIT;
    const int ksta = sp * kt;
    const size_t czoff = (size_t)z * sC;

    const int m0 = blockIdx.y * 128;
    const int n0 = blockIdx.x * 128;

    uint32_t sbase = (uint32_t)__cvta_generic_to_shared(smem);

    // ---- cp.async loader setup: 4 A-chunks + 4 B-chunks (16B each) per thread
    const __half* ag[4];
    const __half* bg[4];
    uint32_t asmo[4], bsmo[4];
#pragma unroll
    for (int i = 0; i < 4; i++) {
        int cid = tid + i * 256;            // 0..1023
        int am = cid >> 3, kc = cid & 7;    // A: row m, 16B-chunk kc (8 halves)
        ag[i] = A + (size_t)(m0 + am) * K + ksta + kc * 8;
        asmo[i] = am * 128 + ((kc ^ (am & 7)) << 4);
        int bk = cid >> 4, bc = cid & 15;   // B: k-row, 16B-chunk bc (8 halves)
        bg[i] = B + (size_t)bb * sB + (size_t)(ksta + bk) * N + n0 + bc * 8;
        bsmo[i] = 16384 + bk * 256 + (((bc & 8) | ((bc & 7) ^ (bk & 7))) << 4);
    }

    float acc[4][4][4];
#pragma unroll
    for (int i = 0; i < 4; i++)
#pragma unroll
        for (int j = 0; j < 4; j++)
#pragma unroll
            for (int q = 0; q < 4; q++) acc[i][j][q] = 0.f;

    const int NC = kt >> 6;   // BK=64 chunks

    // prologue: stages 0, 1
    {
        uint32_t sb = sbase;
#pragma unroll
        for (int i = 0; i < 4; i++) cpasync16(sb + asmo[i], ag[i]);
#pragma unroll
        for (int i = 0; i < 4; i++) cpasync16(sb + bsmo[i], bg[i]);
    }
    CP_COMMIT();
    {
        uint32_t sb = sbase + 32768;
#pragma unroll
        for (int i = 0; i < 4; i++) cpasync16(sb + asmo[i], ag[i] + 64);
#pragma unroll
        for (int i = 0; i < 4; i++) cpasync16(sb + bsmo[i], bg[i] + (size_t)64 * N);
    }
    CP_COMMIT();

    // lane-derived fragment addressing constants
    const int am8 = (lane & 7) + (((lane >> 3) & 1) << 3);  // row within 16-row tile
    const int kq  = lane >> 4;                              // k-half select (0/1)

    for (int c = 0; c < NC; c++) {
        CP_WAIT1();
        __syncthreads();
        if (c + 2 < NC) {
            uint32_t sb = sbase + ((c + 2) % 3) * 32768;
            const int ko = (c + 2) * 64;
#pragma unroll
            for (int i = 0; i < 4; i++) cpasync16(sb + asmo[i], ag[i] + ko);
#pragma unroll
            for (int i = 0; i < 4; i++) cpasync16(sb + bsmo[i], bg[i] + (size_t)ko * N);
        }
        CP_COMMIT();

        uint32_t abase = sbase + (c % 3) * 32768;
        uint32_t bbase = abase + 16384;
#pragma unroll
        for (int ks = 0; ks < 4; ks++) {
            uint4 af[4];
#pragma unroll
            for (int i = 0; i < 4; i++) {
                int m = wr * 64 + i * 16 + am8;
                uint32_t ad = abase + m * 128 + ((((ks * 2 + kq)) ^ (lane & 7)) << 4);
                ldsm4(af[i], ad);
            }
            uint2 bf[4];
#pragma unroll
            for (int jj = 0; jj < 2; jj++) {
                int k = ks * 16 + am8;
                int c2 = wc * 4 + jj * 2 + kq;
                uint32_t bd = bbase + k * 256 +
                              (((c2 & 8) | ((c2 & 7) ^ (lane & 7))) << 4);
                uint32_t r0, r1, r2, r3;
                ldsm4t(r0, r1, r2, r3, bd);
                bf[2 * jj]     = make_uint2(r0, r1);
                bf[2 * jj + 1] = make_uint2(r2, r3);
            }
#pragma unroll
            for (int i = 0; i < 4; i++)
#pragma unroll
                for (int j = 0; j < 4; j++)
                    mma16816(acc[i][j], af[i], bf[j]);
        }
    }

    // ---- epilogue ----
    const int rbase = m0 + wr * 64;
    const int cbase = n0 + wc * 32;
#pragma unroll
    for (int i = 0; i < 4; i++) {
        int row_lo = rbase + i * 16 + (lane >> 2);
        int row_hi = row_lo + 8;
#pragma unroll
        for (int j = 0; j < 4; j++) {
            int col = cbase + j * 8 + (lane & 3) * 2;
            float2 lo = make_float2(acc[i][j][0], acc[i][j][1]);
            float2 hi = make_float2(acc[i][j][2], acc[i][j][3]);
            if (OPT & 64) {
                *(float2*)&C[czoff + (size_t)row_lo * N + col] = lo;
                *(float2*)&C[czoff + (size_t)row_hi * N + col] = hi;
                continue;
            }
            if (OPT & 1) {
                float2 bbv = *(const float2*)&bias[col];
                lo.x += bbv.x; lo.y += bbv.y;
                hi.x += bbv.x; hi.y += bbv.y;
            }
            if (OPT & 2) {
                lo.x = fmaxf(lo.x, 0.f); lo.y = fmaxf(lo.y, 0.f);
                hi.x = fmaxf(hi.x, 0.f); hi.y = fmaxf(hi.y, 0.f);
            }
            if (OPT & 32) {
                *(uint32_t*)&Ch[czoff + (size_t)row_lo * N + col] = packh2(lo.x, lo.y);
                *(uint32_t*)&Ch[czoff + (size_t)row_hi * N + col] = packh2(hi.x, hi.y);
            } else {
                *(float2*)&C[czoff + (size_t)row_lo * N + col] = lo;
                *(float2*)&C[czoff + (size_t)row_hi * N + col] = hi;
            }
        }
    }
}

// ---------------------------------------------------------------------------
// Reduce 4 split-K partials + rscale + residual(x) -> LN -> Hn (f32 + half)
// ---------------------------------------------------------------------------
__global__ void k_red_ln1(const float* __restrict__ x,
                          const float* __restrict__ gw, const float* __restrict__ bw) {
    __shared__ float red[8];
    int r = blockIdx.x;
    int b = r >> 11;
    int m = r & (CL - 1);
    int tid = threadIdx.x;
    size_t rowoff = (size_t)m * CD + tid;
    size_t zstride = (size_t)CL * CD;

    float v = g_part[((size_t)(b * 4 + 0)) * zstride + rowoff]
            + g_part[((size_t)(b * 4 + 1)) * zstride + rowoff]
            + g_part[((size_t)(b * 4 + 2)) * zstride + rowoff]
            + g_part[((size_t)(b * 4 + 3)) * zstride + rowoff];
    v = v * g_invden[b * CL + m] + x[(size_t)r * CD + tid];

    float s = v;
    for (int o = 16; o > 0; o >>= 1) s += __shfl_xor_sync(0xffffffffu, s, o);
    if ((tid & 31) == 0) red[tid >> 5] = s;
    __syncthreads();
    if (tid < 32) {
        float rr = (tid < 8) ? red[tid] : 0.f;
        for (int o = 4; o > 0; o >>= 1) rr += __shfl_xor_sync(0xffffffffu, rr, o);
        if (tid == 0) red[0] = rr;
    }
    __syncthreads();
    float mu = red[0] * (1.f / CD);
    __syncthreads();
    float t = v - mu;
    float s2 = t * t;
    for (int o = 16; o > 0; o >>= 1) s2 += __shfl_xor_sync(0xffffffffu, s2, o);
    if ((tid & 31) == 0) red[tid >> 5] = s2;
    __syncthreads();
    if (tid < 32) {
        float rr = (tid < 8) ? red[tid] : 0.f;
        for (int o = 4; o > 0; o >>= 1) rr += __shfl_xor_sync(0xffffffffu, rr, o);
        if (tid == 0) red[0] = rr;
    }
    __syncthreads();
    float var = red[0] * (1.f / CD);
    float y = t * rsqrtf(var + 1e-5f) * gw[tid] + bw[tid];
    g_Hn[(size_t)r * CD + tid] = y;
    g_Hnh[(size_t)r * CD + tid] = __float2half_rn(y);
}

// ---------------------------------------------------------------------------
// Reduce 4 split-K partials + bias + residual(Hn) -> LN -> out
// ---------------------------------------------------------------------------
__global__ void k_red_ln2(const float* __restrict__ b2,
                          const float* __restrict__ gw, const float* __restrict__ bw,
                          float* __restrict__ out) {
    __shared__ float red[8];
    int r = blockIdx.x;
    int tid = threadIdx.x;
    size_t rowoff = (size_t)r * CD + tid;
    size_t zstride = (size_t)CB * CL * CD;

    float v = g_part[0 * zstride + rowoff] + g_part[1 * zstride + rowoff]
            + g_part[2 * zstride + rowoff] + g_part[3 * zstride + rowoff];
    v += b2[tid] + g_Hn[rowoff];

    float s = v;
    for (int o = 16; o > 0; o >>= 1) s += __shfl_xor_sync(0xffffffffu, s, o);
    if ((tid & 31) == 0) red[tid >> 5] = s;
    __syncthreads();
    if (tid < 32) {
        float rr = (tid < 8) ? red[tid] : 0.f;
        for (int o = 4; o > 0; o >>= 1) rr += __shfl_xor_sync(0xffffffffu, rr, o);
        if (tid == 0) red[0] = rr;
    }
    __syncthreads();
    float mu = red[0] * (1.f / CD);
    __syncthreads();
    float t = v - mu;
    float s2 = t * t;
    for (int o = 16; o > 0; o >>= 1) s2 += __shfl_xor_sync(0xffffffffu, s2, o);
    if ((tid & 31) == 0) red[tid >> 5] = s2;
    __syncthreads();
    if (tid < 32) {
        float rr = (tid < 8) ? red[tid] : 0.f;
        for (int o = 4; o > 0; o >>= 1) rr += __shfl_xor_sync(0xffffffffu, rr, o);
        if (tid == 0) red[0] = rr;
    }
    __syncthreads();
    float var = red[0] * (1.f / CD);
    out[rowoff] = t * rsqrtf(var + 1e-5f) * gw[tid] + bw[tid];
}

// ---------------------------------------------------------------------------
// kernel_launch
// ---------------------------------------------------------------------------
extern "C" void kernel_launch(void* const* d_in, const int* in_sizes, int n_in,
                              void* d_out, int out_size) {
    const float* x    = (const float*)d_in[0];
    const int*   mask = (const int*)  d_in[1];
    const float* W1   = (const float*)d_in[2];
    const float* b1   = (const float*)d_in[3];
    const float* W2   = (const float*)d_in[4];
    const float* b2   = (const float*)d_in[5];
    const float* g1   = (const float*)d_in[6];
    const float* be1  = (const float*)d_in[7];
    const float* g2   = (const float*)d_in[8];
    const float* be2  = (const float*)d_in[9];
    float* out = (float*)d_out;

    __half *pP, *pHnh, *pH1h, *pxh, *pW1h, *pW2h;
    float *pPart;
    cudaGetSymbolAddress((void**)&pP,    g_P);
    cudaGetSymbolAddress((void**)&pPart, g_part);
    cudaGetSymbolAddress((void**)&pHnh,  g_Hnh);
    cudaGetSymbolAddress((void**)&pH1h,  g_H1h);
    cudaGetSymbolAddress((void**)&pxh,   g_xh);
    cudaGetSymbolAddress((void**)&pW1h,  g_W1h);
    cudaGetSymbolAddress((void**)&pW2h,  g_W2h);

    const int DSMEM = 3 * 32768;
    cudaFuncSetAttribute(k_hgemm<64, 4>, cudaFuncAttributeMaxDynamicSharedMemorySize, DSMEM);
    cudaFuncSetAttribute(k_hgemm<35, 1>, cudaFuncAttributeMaxDynamicSharedMemorySize, DSMEM);

    // 1) token mean
    k_mean<<<(CL * CDK + 255) / 256, 256>>>(x);
    // 2) P = half(exp(scores))
    k_scores<<<dim3(CL / 16, CL / 16), dim3(16, 16)>>>();
    // 3) per-batch softmax denominators
    k_denom<<<CL, 256>>>(mask);
    // 4) half conversions (mask folded into xh)
    k_xh<<<(CB * CL * CD / 4) / 256, 256>>>(x, mask);
    k_wh<<<(CD * CF / 4) / 256, 256>>>(W1, pW1h);
    k_wh<<<(CF * CD / 4) / 256, 256>>>(W2, pW2h);

    // 5) GEMM1 split-K4: part[b*4+s] = P[:, ks] @ xh_b[ks, :]  (raw partials)
    k_hgemm<64, 4><<<dim3(CD / 128, CL / 128, CB * 4), 256, DSMEM>>>(
        pP, pxh, nullptr, pPart, nullptr,
        CD, CL, (size_t)CL * CD, (size_t)CL * CD);

    // 6) reduce + invden + residual(x) + LN1 -> Hn, Hnh
    k_red_ln1<<<CB * CL, CD>>>(x, g1, be1);

    // 7) H1h = half(relu(Hn @ W1 + b1))   OPT = 1|2|32
    k_hgemm<35, 1><<<dim3(CF / 128, (CB * CL) / 128, 1), 256, DSMEM>>>(
        pHnh, pW1h, b1, nullptr, pH1h,
        CF, CD, 0, 0);

    // 8) GEMM3 split-K4: part[s] = H1h[:, ks] @ W2h[ks, :]  (raw partials)
    k_hgemm<64, 4><<<dim3(CD / 128, (CB * CL) / 128, 4), 256, DSMEM>>>(
        pH1h, pW2h, nullptr, pPart, nullptr,
        CD, CF, 0, (size_t)CB * CL * CD);

    // 9) reduce + bias + residual(Hn) + LN2 -> out
    k_red_ln2<<<CB * CL, CD>>>(b2, g2, be2, out);
}

// round 12
// speedup vs baseline: 3.4342x; 1.2185x over previous
#include <cuda_runtime.h>
#include <cuda_fp16.h>
#include <math.h>
#include <stdint.h>

// Problem constants (fixed by reference setup_inputs)
#define CB 4
#define CL 2048
#define CD 256
#define CH 8
#define CDK 32
#define CF 1024

// ---------------------------------------------------------------------------
// Scratch (device globals: allocation-free per harness rules)
// ---------------------------------------------------------------------------
__device__ __align__(16) float  g_m[CL * CDK];                   // 256 KB
__device__ __align__(16) __half g_P[(size_t)CL * CL];            // 8 MB : exp(scores)
__device__ __align__(16) float  g_invden[CB * CL];               // 32 KB
__device__ __align__(16) float  g_part[(size_t)8 * CL * CD];     // 16 MB: split-K partials
__device__ __align__(16) float  g_Hn[(size_t)CB * CL * CD];      // 8 MB
__device__ __align__(16) __half g_Hnh[(size_t)CB * CL * CD];     // 4 MB
__device__ __align__(16) __half g_H1h[(size_t)CB * CL * CF];     // 16 MB
__device__ __align__(16) __half g_xh[(size_t)CB * CL * CD];      // 4 MB : masked x, half
__device__ __align__(16) __half g_W1h[(size_t)CD * CF];          // 512 KB
__device__ __align__(16) __half g_W2h[(size_t)CF * CD];          // 512 KB

// ---------------------------------------------------------------------------
// m[l, d] = mean over (b, h) of x[b, l, h*32 + d]
// ---------------------------------------------------------------------------
__global__ void k_mean(const float* __restrict__ x) {
    int idx = blockIdx.x * blockDim.x + threadIdx.x;
    if (idx >= CL * CDK) return;
    int l = idx / CDK;
    int d = idx % CDK;
    float s = 0.f;
#pragma unroll
    for (int b = 0; b < CB; b++)
#pragma unroll
        for (int h = 0; h < CH; h++)
            s += x[((size_t)(b * CL) + l) * CD + h * CDK + d];
    g_m[idx] = s * (1.f / 32.f);
}

// ---------------------------------------------------------------------------
// P[i, j] = half( exp( (1 - cos(clip(m_i . m_j)))/2 ) )   [= exp(sin^2(a/2))]
// 32x32 tile / block of 256, 4 outputs per thread, uint2 half stores.
// ---------------------------------------------------------------------------
__device__ __forceinline__ uint32_t packh2(float lo, float hi) {
    __half2 h = __floats2half2_rn(lo, hi);
    return *(uint32_t*)&h;
}

__global__ void __launch_bounds__(256) k_scores() {
    __shared__ float mi[32][33];
    __shared__ float mj[32][33];
    int i0 = blockIdx.y * 32;
    int j0 = blockIdx.x * 32;
    int tid = threadIdx.x;
    {
        int r = tid >> 3, c4 = (tid & 7) * 4;
        float4 vi = *(const float4*)&g_m[(i0 + r) * CDK + c4];
        mi[r][c4] = vi.x; mi[r][c4 + 1] = vi.y; mi[r][c4 + 2] = vi.z; mi[r][c4 + 3] = vi.w;
        float4 vj = *(const float4*)&g_m[(j0 + r) * CDK + c4];
        mj[r][c4] = vj.x; mj[r][c4 + 1] = vj.y; mj[r][c4 + 2] = vj.z; mj[r][c4 + 3] = vj.w;
    }
    __syncthreads();
    int i = tid >> 3, jb = (tid & 7) * 4;
    float d0 = 0.f, d1 = 0.f, d2 = 0.f, d3 = 0.f;
#pragma unroll
    for (int k = 0; k < 32; k++) {
        float a = mi[i][k];
        d0 = fmaf(a, mj[jb + 0][k], d0);
        d1 = fmaf(a, mj[jb + 1][k], d1);
        d2 = fmaf(a, mj[jb + 2][k], d2);
        d3 = fmaf(a, mj[jb + 3][k], d3);
    }
    const float PI = 3.14159265358979323846f;
    float p0 = __expf(0.5f * (1.f - __cosf(fminf(fmaxf(d0, -PI), PI))));
    float p1 = __expf(0.5f * (1.f - __cosf(fminf(fmaxf(d1, -PI), PI))));
    float p2 = __expf(0.5f * (1.f - __cosf(fminf(fmaxf(d2, -PI), PI))));
    float p3 = __expf(0.5f * (1.f - __cosf(fminf(fmaxf(d3, -PI), PI))));
    uint2 o;
    o.x = packh2(p0, p1);
    o.y = packh2(p2, p3);
    *(uint2*)&g_P[(size_t)(i0 + i) * CL + j0 + jb] = o;
}

// ---------------------------------------------------------------------------
// invden[b][i] = 1 / sum_j P[i,j] * (mask[b][j] != 0)
// ---------------------------------------------------------------------------
__global__ void k_denom(const int* __restrict__ mask) {
    __shared__ float red[CB][8];
    int i = blockIdx.x;
    int tid = threadIdx.x;  // 256
    const __half2* Prow = (const __half2*)(g_P + (size_t)i * CL);
    float acc[CB] = {0.f, 0.f, 0.f, 0.f};
    for (int j2 = tid; j2 < CL / 2; j2 += 256) {
        float2 pf = __half22float2(Prow[j2]);
        int j = j2 * 2;
#pragma unroll
        for (int b = 0; b < CB; b++) {
            acc[b] += (mask[b * CL + j] != 0) ? pf.x : 0.f;
            acc[b] += (mask[b * CL + j + 1] != 0) ? pf.y : 0.f;
        }
    }
#pragma unroll
    for (int b = 0; b < CB; b++) {
        float v = acc[b];
        for (int o = 16; o > 0; o >>= 1) v += __shfl_xor_sync(0xffffffffu, v, o);
        if ((tid & 31) == 0) red[b][tid >> 5] = v;
    }
    __syncthreads();
    if (tid < CB) {
        float s = 0.f;
#pragma unroll
        for (int w = 0; w < 8; w++) s += red[tid][w];
        g_invden[tid * CL + i] = 1.f / s;
    }
}

// ---------------------------------------------------------------------------
// Half conversions (16 elems / thread for MLP)
// ---------------------------------------------------------------------------
__global__ void k_xh(const float* __restrict__ x, const int* __restrict__ mask) {
    size_t e = (size_t)(blockIdx.x * 256 + threadIdx.x) * 16;
    int msk = mask[e >> 8];          // 16 elems stay inside one 256-wide row
    float4 v[4];
#pragma unroll
    for (int u = 0; u < 4; u++) v[u] = *(const float4*)&x[e + u * 4];
#pragma unroll
    for (int u = 0; u < 4; u++) {
        if (!msk) v[u] = make_float4(0.f, 0.f, 0.f, 0.f);
        uint2 o;
        o.x = packh2(v[u].x, v[u].y);
        o.y = packh2(v[u].z, v[u].w);
        *(uint2*)&g_xh[e + u * 4] = o;
    }
}

__global__ void k_wh(const float* __restrict__ w, __half* __restrict__ out) {
    size_t e = (size_t)(blockIdx.x * 256 + threadIdx.x) * 16;
    float4 v[4];
#pragma unroll
    for (int u = 0; u < 4; u++) v[u] = *(const float4*)&w[e + u * 4];
#pragma unroll
    for (int u = 0; u < 4; u++) {
        uint2 o;
        o.x = packh2(v[u].x, v[u].y);
        o.y = packh2(v[u].z, v[u].w);
        *(uint2*)&out[e + u * 4] = o;
    }
}

// ---------------------------------------------------------------------------
// mma / ldmatrix / cp.async helpers
// ---------------------------------------------------------------------------
__device__ __forceinline__ void mma16816(float* d, const uint4& a, const uint2& b) {
    asm volatile(
        "mma.sync.aligned.m16n8k16.row.col.f32.f16.f16.f32 "
        "{%0,%1,%2,%3}, {%4,%5,%6,%7}, {%8,%9}, {%0,%1,%2,%3};"
        : "+f"(d[0]), "+f"(d[1]), "+f"(d[2]), "+f"(d[3])
        : "r"(a.x), "r"(a.y), "r"(a.z), "r"(a.w), "r"(b.x), "r"(b.y));
}
__device__ __forceinline__ void ldsm4(uint4& d, uint32_t a) {
    asm volatile("ldmatrix.sync.aligned.m8n8.x4.shared.b16 {%0,%1,%2,%3}, [%4];"
        : "=r"(d.x), "=r"(d.y), "=r"(d.z), "=r"(d.w) : "r"(a));
}
__device__ __forceinline__ void ldsm4t(uint32_t& r0, uint32_t& r1,
                                       uint32_t& r2, uint32_t& r3, uint32_t a) {
    asm volatile("ldmatrix.sync.aligned.m8n8.x4.trans.shared.b16 {%0,%1,%2,%3}, [%4];"
        : "=r"(r0), "=r"(r1), "=r"(r2), "=r"(r3) : "r"(a));
}
__device__ __forceinline__ void cpasync16(uint32_t s, const void* g) {
    asm volatile("cp.async.cg.shared.global [%0], [%1], 16;" :: "r"(s), "l"(g));
}
#define CP_COMMIT() asm volatile("cp.async.commit_group;" ::: "memory")
#define CP_WAIT1()  asm volatile("cp.async.wait_group 1;" ::: "memory")

// ---------------------------------------------------------------------------
// FP16 tensor-core GEMM (cp.async 3-stage + ldmatrix):
//   C[M,N] = A[M,K] @ B[K,N], A half K-major, B half [K][N] row-major.
// CTA tile 128x128, BK=64, 8 warps (2x4), warp tile 64x32 via m16n8k16.
// blockIdx.z = b * SPLIT + s (split-K).
// OPT bits: 1=+bias, 2=relu, 32=half C out, 64=raw fp32 partial out
// ---------------------------------------------------------------------------
template <int OPT, int SPLIT>
__global__ void __launch_bounds__(256, 2) k_hgemm(
    const __half* __restrict__ A, const __half* __restrict__ B,
    const float* __restrict__ bias,
    float* __restrict__ C, __half* __restrict__ Ch,
    int N, int K, size_t sB, size_t sC)
{
    extern __shared__ __align__(128) char smem[];
    const int tid = threadIdx.x;
    const int lane = tid & 31;
    const int wid = tid >> 5;
    const int wr = wid >> 2;       // warp row (0..1) -> 64 rows
    const int wc = wid & 3;        // warp col (0..3) -> 32 cols

    const int z = blockIdx.z;
    const int bb = z / SPLIT;
    const int sp = z % SPLIT;
    const int kt = K / SPLIT;
    const int ksta = sp * kt;
    const size_t czoff = (size_t)z * sC;

    const int m0 = blockIdx.y * 128;
    const int n0 = blockIdx.x * 128;

    uint32_t sbase = (uint32_t)__cvta_generic_to_shared(smem);

    // ---- cp.async loader setup: 4 A-chunks + 4 B-chunks (16B each) per thread
    const __half* ag[4];
    const __half* bg[4];
    uint32_t asmo[4], bsmo[4];
#pragma unroll
    for (int i = 0; i < 4; i++) {
        int cid = tid + i * 256;            // 0..1023
        int am = cid >> 3, kc = cid & 7;    // A: row m, 16B-chunk kc (8 halves)
        ag[i] = A + (size_t)(m0 + am) * K + ksta + kc * 8;
        asmo[i] = am * 128 + ((kc ^ (am & 7)) << 4);
        int bk = cid >> 4, bc = cid & 15;   // B: k-row, 16B-chunk bc (8 halves)
        bg[i] = B + (size_t)bb * sB + (size_t)(ksta + bk) * N + n0 + bc * 8;
        bsmo[i] = 16384 + bk * 256 + (((bc & 8) | ((bc & 7) ^ (bk & 7))) << 4);
    }

    float acc[4][4][4];
#pragma unroll
    for (int i = 0; i < 4; i++)
#pragma unroll
        for (int j = 0; j < 4; j++)
#pragma unroll
            for (int q = 0; q < 4; q++) acc[i][j][q] = 0.f;

    const int NC = kt >> 6;   // BK=64 chunks

    // prologue: stages 0, 1
    {
        uint32_t sb = sbase;
#pragma unroll
        for (int i = 0; i < 4; i++) cpasync16(sb + asmo[i], ag[i]);
#pragma unroll
        for (int i = 0; i < 4; i++) cpasync16(sb + bsmo[i], bg[i]);
    }
    CP_COMMIT();
    {
        uint32_t sb = sbase + 32768;
#pragma unroll
        for (int i = 0; i < 4; i++) cpasync16(sb + asmo[i], ag[i] + 64);
#pragma unroll
        for (int i = 0; i < 4; i++) cpasync16(sb + bsmo[i], bg[i] + (size_t)64 * N);
    }
    CP_COMMIT();

    const int am8 = (lane & 7) + (((lane >> 3) & 1) << 3);
    const int kq  = lane >> 4;

    for (int c = 0; c < NC; c++) {
        CP_WAIT1();
        __syncthreads();
        if (c + 2 < NC) {
            uint32_t sb = sbase + ((c + 2) % 3) * 32768;
            const int ko = (c + 2) * 64;
#pragma unroll
            for (int i = 0; i < 4; i++) cpasync16(sb + asmo[i], ag[i] + ko);
#pragma unroll
            for (int i = 0; i < 4; i++) cpasync16(sb + bsmo[i], bg[i] + (size_t)ko * N);
        }
        CP_COMMIT();

        uint32_t abase = sbase + (c % 3) * 32768;
        uint32_t bbase = abase + 16384;
#pragma unroll
        for (int ks = 0; ks < 4; ks++) {
            uint4 af[4];
#pragma unroll
            for (int i = 0; i < 4; i++) {
                int m = wr * 64 + i * 16 + am8;
                uint32_t ad = abase + m * 128 + ((((ks * 2 + kq)) ^ (lane & 7)) << 4);
                ldsm4(af[i], ad);
            }
            uint2 bf[4];
#pragma unroll
            for (int jj = 0; jj < 2; jj++) {
                int k = ks * 16 + am8;
                int c2 = wc * 4 + jj * 2 + kq;
                uint32_t bd = bbase + k * 256 +
                              (((c2 & 8) | ((c2 & 7) ^ (lane & 7))) << 4);
                uint32_t r0, r1, r2, r3;
                ldsm4t(r0, r1, r2, r3, bd);
                bf[2 * jj]     = make_uint2(r0, r1);
                bf[2 * jj + 1] = make_uint2(r2, r3);
            }
#pragma unroll
            for (int i = 0; i < 4; i++)
#pragma unroll
                for (int j = 0; j < 4; j++)
                    mma16816(acc[i][j], af[i], bf[j]);
        }
    }

    // ---- epilogue ----
    const int rbase = m0 + wr * 64;
    const int cbase = n0 + wc * 32;
#pragma unroll
    for (int i = 0; i < 4; i++) {
        int row_lo = rbase + i * 16 + (lane >> 2);
        int row_hi = row_lo + 8;
#pragma unroll
        for (int j = 0; j < 4; j++) {
            int col = cbase + j * 8 + (lane & 3) * 2;
            float2 lo = make_float2(acc[i][j][0], acc[i][j][1]);
            float2 hi = make_float2(acc[i][j][2], acc[i][j][3]);
            if (OPT & 64) {
                *(float2*)&C[czoff + (size_t)row_lo * N + col] = lo;
                *(float2*)&C[czoff + (size_t)row_hi * N + col] = hi;
                continue;
            }
            if (OPT & 1) {
                float2 bbv = *(const float2*)&bias[col];
                lo.x += bbv.x; lo.y += bbv.y;
                hi.x += bbv.x; hi.y += bbv.y;
            }
            if (OPT & 2) {
                lo.x = fmaxf(lo.x, 0.f); lo.y = fmaxf(lo.y, 0.f);
                hi.x = fmaxf(hi.x, 0.f); hi.y = fmaxf(hi.y, 0.f);
            }
            if (OPT & 32) {
                *(uint32_t*)&Ch[czoff + (size_t)row_lo * N + col] = packh2(lo.x, lo.y);
                *(uint32_t*)&Ch[czoff + (size_t)row_hi * N + col] = packh2(hi.x, hi.y);
            } else {
                *(float2*)&C[czoff + (size_t)row_lo * N + col] = lo;
                *(float2*)&C[czoff + (size_t)row_hi * N + col] = hi;
            }
        }
    }
}

// ---------------------------------------------------------------------------
// Reduce 2 split-K partials + invden + residual(x) -> LN -> Hn (f32 + half)
// ---------------------------------------------------------------------------
__global__ void k_red_ln1(const float* __restrict__ x,
                          const float* __restrict__ gw, const float* __restrict__ bw) {
    __shared__ float red[8];
    int r = blockIdx.x;
    int b = r >> 11;
    int m = r & (CL - 1);
    int tid = threadIdx.x;
    size_t rowoff = (size_t)m * CD + tid;
    size_t zstride = (size_t)CL * CD;

    float v = g_part[((size_t)(b * 2 + 0)) * zstride + rowoff]
            + g_part[((size_t)(b * 2 + 1)) * zstride + rowoff];
    v = v * g_invden[b * CL + m] + x[(size_t)r * CD + tid];

    float s = v;
    for (int o = 16; o > 0; o >>= 1) s += __shfl_xor_sync(0xffffffffu, s, o);
    if ((tid & 31) == 0) red[tid >> 5] = s;
    __syncthreads();
    if (tid < 32) {
        float rr = (tid < 8) ? red[tid] : 0.f;
        for (int o = 4; o > 0; o >>= 1) rr += __shfl_xor_sync(0xffffffffu, rr, o);
        if (tid == 0) red[0] = rr;
    }
    __syncthreads();
    float mu = red[0] * (1.f / CD);
    __syncthreads();
    float t = v - mu;
    float s2 = t * t;
    for (int o = 16; o > 0; o >>= 1) s2 += __shfl_xor_sync(0xffffffffu, s2, o);
    if ((tid & 31) == 0) red[tid >> 5] = s2;
    __syncthreads();
    if (tid < 32) {
        float rr = (tid < 8) ? red[tid] : 0.f;
        for (int o = 4; o > 0; o >>= 1) rr += __shfl_xor_sync(0xffffffffu, rr, o);
        if (tid == 0) red[0] = rr;
    }
    __syncthreads();
    float var = red[0] * (1.f / CD);
    float y = t * rsqrtf(var + 1e-5f) * gw[tid] + bw[tid];
    g_Hn[(size_t)r * CD + tid] = y;
    g_Hnh[(size_t)r * CD + tid] = __float2half_rn(y);
}

// ---------------------------------------------------------------------------
// Reduce 2 split-K partials + bias + residual(Hn) -> LN -> out
// ---------------------------------------------------------------------------
__global__ void k_red_ln2(const float* __restrict__ b2,
                          const float* __restrict__ gw, const float* __restrict__ bw,
                          float* __restrict__ out) {
    __shared__ float red[8];
    int r = blockIdx.x;
    int tid = threadIdx.x;
    size_t rowoff = (size_t)r * CD + tid;
    size_t zstride = (size_t)CB * CL * CD;

    float v = g_part[0 * zstride + rowoff] + g_part[1 * zstride + rowoff];
    v += b2[tid] + g_Hn[rowoff];

    float s = v;
    for (int o = 16; o > 0; o >>= 1) s += __shfl_xor_sync(0xffffffffu, s, o);
    if ((tid & 31) == 0) red[tid >> 5] = s;
    __syncthreads();
    if (tid < 32) {
        float rr = (tid < 8) ? red[tid] : 0.f;
        for (int o = 4; o > 0; o >>= 1) rr += __shfl_xor_sync(0xffffffffu, rr, o);
        if (tid == 0) red[0] = rr;
    }
    __syncthreads();
    float mu = red[0] * (1.f / CD);
    __syncthreads();
    float t = v - mu;
    float s2 = t * t;
    for (int o = 16; o > 0; o >>= 1) s2 += __shfl_xor_sync(0xffffffffu, s2, o);
    if ((tid & 31) == 0) red[tid >> 5] = s2;
    __syncthreads();
    if (tid < 32) {
        float rr = (tid < 8) ? red[tid] : 0.f;
        for (int o = 4; o > 0; o >>= 1) rr += __shfl_xor_sync(0xffffffffu, rr, o);
        if (tid == 0) red[0] = rr;
    }
    __syncthreads();
    float var = red[0] * (1.f / CD);
    out[rowoff] = t * rsqrtf(var + 1e-5f) * gw[tid] + bw[tid];
}

// ---------------------------------------------------------------------------
// kernel_launch
// ---------------------------------------------------------------------------
extern "C" void kernel_launch(void* const* d_in, const int* in_sizes, int n_in,
                              void* d_out, int out_size) {
    const float* x    = (const float*)d_in[0];
    const int*   mask = (const int*)  d_in[1];
    const float* W1   = (const float*)d_in[2];
    const float* b1   = (const float*)d_in[3];
    const float* W2   = (const float*)d_in[4];
    const float* b2   = (const float*)d_in[5];
    const float* g1   = (const float*)d_in[6];
    const float* be1  = (const float*)d_in[7];
    const float* g2   = (const float*)d_in[8];
    const float* be2  = (const float*)d_in[9];
    float* out = (float*)d_out;

    __half *pP, *pHnh, *pH1h, *pxh, *pW1h, *pW2h;
    float *pPart;
    cudaGetSymbolAddress((void**)&pP,    g_P);
    cudaGetSymbolAddress((void**)&pPart, g_part);
    cudaGetSymbolAddress((void**)&pHnh,  g_Hnh);
    cudaGetSymbolAddress((void**)&pH1h,  g_H1h);
    cudaGetSymbolAddress((void**)&pxh,   g_xh);
    cudaGetSymbolAddress((void**)&pW1h,  g_W1h);
    cudaGetSymbolAddress((void**)&pW2h,  g_W2h);

    const int DSMEM = 3 * 32768;
    cudaFuncSetAttribute(k_hgemm<64, 2>, cudaFuncAttributeMaxDynamicSharedMemorySize, DSMEM);
    cudaFuncSetAttribute(k_hgemm<35, 1>, cudaFuncAttributeMaxDynamicSharedMemorySize, DSMEM);

    // 1) token mean
    k_mean<<<(CL * CDK + 255) / 256, 256>>>(x);
    // 2) P = half(exp(sin^2)) via cos identity
    k_scores<<<dim3(CL / 32, CL / 32), 256>>>();
    // 3) per-batch softmax denominators
    k_denom<<<CL, 256>>>(mask);
    // 4) half conversions (mask folded into xh)
    k_xh<<<(CB * CL * CD / 16) / 256, 256>>>(x, mask);
    k_wh<<<(CD * CF / 16) / 256, 256>>>(W1, pW1h);
    k_wh<<<(CF * CD / 16) / 256, 256>>>(W2, pW2h);

    // 5) GEMM1 split-K2: part[b*2+s] = P[:, ks] @ xh_b[ks, :]  (raw partials)
    k_hgemm<64, 2><<<dim3(CD / 128, CL / 128, CB * 2), 256, DSMEM>>>(
        pP, pxh, nullptr, pPart, nullptr,
        CD, CL, (size_t)CL * CD, (size_t)CL * CD);

    // 6) reduce + invden + residual(x) + LN1 -> Hn, Hnh
    k_red_ln1<<<CB * CL, CD>>>(x, g1, be1);

    // 7) H1h = half(relu(Hn @ W1 + b1))   OPT = 1|2|32
    k_hgemm<35, 1><<<dim3(CF / 128, (CB * CL) / 128, 1), 256, DSMEM>>>(
        pHnh, pW1h, b1, nullptr, pH1h,
        CF, CD, 0, 0);

    // 8) GEMM3 split-K2: part[s] = H1h[:, ks] @ W2h[ks, :]  (raw partials)
    k_hgemm<64, 2><<<dim3(CD / 128, (CB * CL) / 128, 2), 256, DSMEM>>>(
        pH1h, pW2h, nullptr, pPart, nullptr,
        CD, CF, 0, (size_t)CB * CL * CD);

    // 9) reduce + bias + residual(Hn) + LN2 -> out
    k_red_ln2<<<CB * CL, CD>>>(b2, g2, be2, out);
}

// round 14
// speedup vs baseline: 4.0498x; 1.1792x over previous
#include <cuda_runtime.h>
#include <cuda_fp16.h>
#include <math.h>
#include <stdint.h>

// Problem constants (fixed by reference setup_inputs)
#define CB 4
#define CL 2048
#define CD 256
#define CH 8
#define CDK 32
#define CF 1024

// ---------------------------------------------------------------------------
// Scratch (device globals: allocation-free per harness rules)
// ---------------------------------------------------------------------------
__device__ __align__(16) __half g_mh[CL * CDK];                  // 128 KB
__device__ __align__(16) __half g_P[(size_t)CL * CL];            // 8 MB : exp(scores)
__device__ __align__(16) float  g_den[CB * CL];                  // 32 KB
__device__ __align__(16) float  g_part[(size_t)8 * CL * CD];     // 16 MB: split-K partials
__device__ __align__(16) float  g_Hn[(size_t)CB * CL * CD];      // 8 MB
__device__ __align__(16) __half g_Hnh[(size_t)CB * CL * CD];     // 4 MB
__device__ __align__(16) __half g_H1h[(size_t)CB * CL * CF];     // 16 MB
__device__ __align__(16) __half g_xh[(size_t)CB * CL * CD];      // 4 MB : masked x, half
__device__ __align__(16) __half g_W1h[(size_t)CD * CF];          // 512 KB
__device__ __align__(16) __half g_W2h[(size_t)CF * CD];          // 512 KB

__device__ __forceinline__ uint32_t packh2(float lo, float hi) {
    __half2 h = __floats2half2_rn(lo, hi);
    return *(uint32_t*)&h;
}

// ---------------------------------------------------------------------------
// mh[l, d] = half( mean over (b, h) of x[b, l, h*32 + d] )
// ---------------------------------------------------------------------------
__global__ void k_mean(const float* __restrict__ x) {
    int idx = blockIdx.x * blockDim.x + threadIdx.x;
    if (idx >= CL * CDK) return;
    int l = idx / CDK;
    int d = idx % CDK;
    float s = 0.f;
#pragma unroll
    for (int b = 0; b < CB; b++)
#pragma unroll
        for (int h = 0; h < CH; h++)
            s += x[((size_t)(b * CL) + l) * CD + h * CDK + d];
    g_mh[idx] = __float2half_rn(s * (1.f / 32.f));
}

// ---------------------------------------------------------------------------
// zero g_den
// ---------------------------------------------------------------------------
__global__ void k_zero() {
    g_den[blockIdx.x * 256 + threadIdx.x] = 0.f;
}

// ---------------------------------------------------------------------------
// mma / ldmatrix / cp.async helpers
// ---------------------------------------------------------------------------
__device__ __forceinline__ void mma16816(float* d, const uint4& a, const uint2& b) {
    asm volatile(
        "mma.sync.aligned.m16n8k16.row.col.f32.f16.f16.f32 "
        "{%0,%1,%2,%3}, {%4,%5,%6,%7}, {%8,%9}, {%0,%1,%2,%3};"
        : "+f"(d[0]), "+f"(d[1]), "+f"(d[2]), "+f"(d[3])
        : "r"(a.x), "r"(a.y), "r"(a.z), "r"(a.w), "r"(b.x), "r"(b.y));
}
__device__ __forceinline__ void ldsm4(uint4& d, uint32_t a) {
    asm volatile("ldmatrix.sync.aligned.m8n8.x4.shared.b16 {%0,%1,%2,%3}, [%4];"
        : "=r"(d.x), "=r"(d.y), "=r"(d.z), "=r"(d.w) : "r"(a));
}
__device__ __forceinline__ void ldsm4t(uint32_t& r0, uint32_t& r1,
                                       uint32_t& r2, uint32_t& r3, uint32_t a) {
    asm volatile("ldmatrix.sync.aligned.m8n8.x4.trans.shared.b16 {%0,%1,%2,%3}, [%4];"
        : "=r"(r0), "=r"(r1), "=r"(r2), "=r"(r3) : "r"(a));
}
__device__ __forceinline__ void cpasync16(uint32_t s, const void* g) {
    asm volatile("cp.async.cg.shared.global [%0], [%1], 16;" :: "r"(s), "l"(g));
}
#define CP_COMMIT() asm volatile("cp.async.commit_group;" ::: "memory")
#define CP_WAIT1()  asm volatile("cp.async.wait_group 1;" ::: "memory")

// ---------------------------------------------------------------------------
// Tensor-core scores: P = exp(sin^2(clip(mh @ mh^T)/2)) (half) + fused
// masked row-sum denominators (atomicAdd into g_den).
// 128x128 tile per CTA, 8 warps (2x4), warp tile 64x32, K=32 (2 k-steps).
// ---------------------------------------------------------------------------
__global__ void __launch_bounds__(256) k_scores_mma(const int* __restrict__ mask) {
    __shared__ __align__(16) __half sA[128 * 40];   // 80B row stride
    __shared__ __align__(16) __half sB[128 * 40];
    __shared__ float mk[CB][128];

    const int tid = threadIdx.x;
    const int lane = tid & 31;
    const int wid = tid >> 5;
    const int wr = wid >> 2;        // 0..1 -> 64 rows
    const int wc = wid & 3;         // 0..3 -> 32 cols
    const int i0 = blockIdx.y * 128;
    const int j0 = blockIdx.x * 128;

    // load m tiles (each thread: 2 chunks of 16B for A and B)
#pragma unroll
    for (int u = 0; u < 2; u++) {
        int cid = tid + u * 256;        // 0..511
        int r = cid >> 2, c = cid & 3;  // row, 16B chunk
        *(uint4*)&sA[r * 40 + c * 8] = *(const uint4*)&g_mh[(i0 + r) * CDK + c * 8];
        *(uint4*)&sB[r * 40 + c * 8] = *(const uint4*)&g_mh[(j0 + r) * CDK + c * 8];
    }
    // mask tile: mk[b][jlocal]
    {
        int b = tid >> 6, j = (tid & 63) * 2;
        mk[b][j]     = (mask[b * CL + j0 + j] != 0) ? 1.f : 0.f;
        mk[b][j + 1] = (mask[b * CL + j0 + j + 1] != 0) ? 1.f : 0.f;
    }
    __syncthreads();

    uint32_t aS = (uint32_t)__cvta_generic_to_shared(sA);
    uint32_t bS = (uint32_t)__cvta_generic_to_shared(sB);

    const int am8 = (lane & 7) + (((lane >> 3) & 1) << 3);
    const int kq  = lane >> 4;

    float acc[4][4][4];
#pragma unroll
    for (int i = 0; i < 4; i++)
#pragma unroll
        for (int j = 0; j < 4; j++)
#pragma unroll
            for (int q = 0; q < 4; q++) acc[i][j][q] = 0.f;

#pragma unroll
    for (int ks = 0; ks < 2; ks++) {
        uint4 af[4];
#pragma unroll
        for (int i = 0; i < 4; i++) {
            int m = wr * 64 + i * 16 + am8;
            ldsm4(af[i], aS + m * 80 + (ks * 2 + kq) * 16);
        }
        uint2 bf[4];
#pragma unroll
        for (int jj = 0; jj < 2; jj++) {
            int n = wc * 32 + jj * 16 + am8;
            uint4 t;
            ldsm4(t, bS + n * 80 + (ks * 2 + kq) * 16);
            bf[jj * 2]     = make_uint2(t.x, t.z);   // n0-7: k-lo, k-hi
            bf[jj * 2 + 1] = make_uint2(t.y, t.w);   // n8-15
        }
#pragma unroll
        for (int i = 0; i < 4; i++)
#pragma unroll
            for (int j = 0; j < 4; j++)
                mma16816(acc[i][j], af[i], bf[j]);
    }

    // epilogue: P = exp((1-cos(clip))/2), store half, fused masked row sums
    const float PI = 3.14159265358979323846f;
#pragma unroll
    for (int i = 0; i < 4; i++) {
        int row_lo = i0 + wr * 64 + i * 16 + (lane >> 2);
        int row_hi = row_lo + 8;
        float slo[CB] = {0.f, 0.f, 0.f, 0.f};
        float shi[CB] = {0.f, 0.f, 0.f, 0.f};
#pragma unroll
        for (int j = 0; j < 4; j++) {
            int cl = wc * 32 + j * 8 + (lane & 3) * 2;   // local col 0..127
            float p0 = __expf(0.5f * (1.f - __cosf(fminf(fmaxf(acc[i][j][0], -PI), PI))));
            float p1 = __expf(0.5f * (1.f - __cosf(fminf(fmaxf(acc[i][j][1], -PI), PI))));
            float p2 = __expf(0.5f * (1.f - __cosf(fminf(fmaxf(acc[i][j][2], -PI), PI))));
            float p3 = __expf(0.5f * (1.f - __cosf(fminf(fmaxf(acc[i][j][3], -PI), PI))));
            uint32_t wlo = packh2(p0, p1);
            uint32_t whi = packh2(p2, p3);
            *(uint32_t*)&g_P[(size_t)row_lo * CL + j0 + cl] = wlo;
            *(uint32_t*)&g_P[(size_t)row_hi * CL + j0 + cl] = whi;
            // use the half-rounded values for the denominator (matches GEMM1)
            float2 flo = __half22float2(*(__half2*)&wlo);
            float2 fhi = __half22float2(*(__half2*)&whi);
#pragma unroll
            for (int b = 0; b < CB; b++) {
                slo[b] += flo.x * mk[b][cl] + flo.y * mk[b][cl + 1];
                shi[b] += fhi.x * mk[b][cl] + fhi.y * mk[b][cl + 1];
            }
        }
#pragma unroll
        for (int b = 0; b < CB; b++) {
            slo[b] += __shfl_xor_sync(0xffffffffu, slo[b], 1);
            slo[b] += __shfl_xor_sync(0xffffffffu, slo[b], 2);
            shi[b] += __shfl_xor_sync(0xffffffffu, shi[b], 1);
            shi[b] += __shfl_xor_sync(0xffffffffu, shi[b], 2);
        }
        if ((lane & 3) == 0) {
#pragma unroll
            for (int b = 0; b < CB; b++) {
                atomicAdd(&g_den[b * CL + row_lo], slo[b]);
                atomicAdd(&g_den[b * CL + row_hi], shi[b]);
            }
        }
    }
}

// ---------------------------------------------------------------------------
// Half conversions (16 elems / thread)
// ---------------------------------------------------------------------------
__global__ void k_xh(const float* __restrict__ x, const int* __restrict__ mask) {
    size_t e = (size_t)(blockIdx.x * 256 + threadIdx.x) * 16;
    int msk = mask[e >> 8];
    float4 v[4];
#pragma unroll
    for (int u = 0; u < 4; u++) v[u] = *(const float4*)&x[e + u * 4];
#pragma unroll
    for (int u = 0; u < 4; u++) {
        if (!msk) v[u] = make_float4(0.f, 0.f, 0.f, 0.f);
        uint2 o;
        o.x = packh2(v[u].x, v[u].y);
        o.y = packh2(v[u].z, v[u].w);
        *(uint2*)&g_xh[e + u * 4] = o;
    }
}

__global__ void k_wh(const float* __restrict__ w, __half* __restrict__ out) {
    size_t e = (size_t)(blockIdx.x * 256 + threadIdx.x) * 16;
    float4 v[4];
#pragma unroll
    for (int u = 0; u < 4; u++) v[u] = *(const float4*)&w[e + u * 4];
#pragma unroll
    for (int u = 0; u < 4; u++) {
        uint2 o;
        o.x = packh2(v[u].x, v[u].y);
        o.y = packh2(v[u].z, v[u].w);
        *(uint2*)&out[e + u * 4] = o;
    }
}

// ---------------------------------------------------------------------------
// FP16 tensor-core GEMM (cp.async 3-stage + ldmatrix):
//   C[M,N] = A[M,K] @ B[K,N], A half K-major, B half [K][N] row-major.
// CTA tile 128x128, BK=64, 8 warps (2x4), warp tile 64x32 via m16n8k16.
// blockIdx.z = b * SPLIT + s (split-K).
// OPT bits: 1=+bias, 2=relu, 32=half C out, 64=raw fp32 partial out
// ---------------------------------------------------------------------------
template <int OPT, int SPLIT>
__global__ void __launch_bounds__(256, 2) k_hgemm(
    const __half* __restrict__ A, const __half* __restrict__ B,
    const float* __restrict__ bias,
    float* __restrict__ C, __half* __restrict__ Ch,
    int N, int K, size_t sB, size_t sC)
{
    extern __shared__ __align__(128) char smem[];
    const int tid = threadIdx.x;
    const int lane = tid & 31;
    const int wid = tid >> 5;
    const int wr = wid >> 2;
    const int wc = wid & 3;

    const int z = blockIdx.z;
    const int bb = z / SPLIT;
    const int sp = z % SPLIT;
    const int kt = K / SPLIT;
    const int ksta = sp * kt;
    const size_t czoff = (size_t)z * sC;

    const int m0 = blockIdx.y * 128;
    const int n0 = blockIdx.x * 128;

    uint32_t sbase = (uint32_t)__cvta_generic_to_shared(smem);

    const __half* ag[4];
    const __half* bg[4];
    uint32_t asmo[4], bsmo[4];
#pragma unroll
    for (int i = 0; i < 4; i++) {
        int cid = tid + i * 256;
        int am = cid >> 3, kc = cid & 7;
        ag[i] = A + (size_t)(m0 + am) * K + ksta + kc * 8;
        asmo[i] = am * 128 + ((kc ^ (am & 7)) << 4);
        int bk = cid >> 4, bc = cid & 15;
        bg[i] = B + (size_t)bb * sB + (size_t)(ksta + bk) * N + n0 + bc * 8;
        bsmo[i] = 16384 + bk * 256 + (((bc & 8) | ((bc & 7) ^ (bk & 7))) << 4);
    }

    float acc[4][4][4];
#pragma unroll
    for (int i = 0; i < 4; i++)
#pragma unroll
        for (int j = 0; j < 4; j++)
#pragma unroll
            for (int q = 0; q < 4; q++) acc[i][j][q] = 0.f;

    const int NC = kt >> 6;

    {
        uint32_t sb = sbase;
#pragma unroll
        for (int i = 0; i < 4; i++) cpasync16(sb + asmo[i], ag[i]);
#pragma unroll
        for (int i = 0; i < 4; i++) cpasync16(sb + bsmo[i], bg[i]);
    }
    CP_COMMIT();
    {
        uint32_t sb = sbase + 32768;
#pragma unroll
        for (int i = 0; i < 4; i++) cpasync16(sb + asmo[i], ag[i] + 64);
#pragma unroll
        for (int i = 0; i < 4; i++) cpasync16(sb + bsmo[i], bg[i] + (size_t)64 * N);
    }
    CP_COMMIT();

    const int am8 = (lane & 7) + (((lane >> 3) & 1) << 3);
    const int kq  = lane >> 4;

    for (int c = 0; c < NC; c++) {
        CP_WAIT1();
        __syncthreads();
        if (c + 2 < NC) {
            uint32_t sb = sbase + ((c + 2) % 3) * 32768;
            const int ko = (c + 2) * 64;
#pragma unroll
            for (int i = 0; i < 4; i++) cpasync16(sb + asmo[i], ag[i] + ko);
#pragma unroll
            for (int i = 0; i < 4; i++) cpasync16(sb + bsmo[i], bg[i] + (size_t)ko * N);
        }
        CP_COMMIT();

        uint32_t abase = sbase + (c % 3) * 32768;
        uint32_t bbase = abase + 16384;
#pragma unroll
        for (int ks = 0; ks < 4; ks++) {
            uint4 af[4];
#pragma unroll
            for (int i = 0; i < 4; i++) {
                int m = wr * 64 + i * 16 + am8;
                uint32_t ad = abase + m * 128 + ((((ks * 2 + kq)) ^ (lane & 7)) << 4);
                ldsm4(af[i], ad);
            }
            uint2 bf[4];
#pragma unroll
            for (int jj = 0; jj < 2; jj++) {
                int k = ks * 16 + am8;
                int c2 = wc * 4 + jj * 2 + kq;
                uint32_t bd = bbase + k * 256 +
                              (((c2 & 8) | ((c2 & 7) ^ (lane & 7))) << 4);
                uint32_t r0, r1, r2, r3;
                ldsm4t(r0, r1, r2, r3, bd);
                bf[2 * jj]     = make_uint2(r0, r1);
                bf[2 * jj + 1] = make_uint2(r2, r3);
            }
#pragma unroll
            for (int i = 0; i < 4; i++)
#pragma unroll
                for (int j = 0; j < 4; j++)
                    mma16816(acc[i][j], af[i], bf[j]);
        }
    }

    const int rbase = m0 + wr * 64;
    const int cbase = n0 + wc * 32;
#pragma unroll
    for (int i = 0; i < 4; i++) {
        int row_lo = rbase + i * 16 + (lane >> 2);
        int row_hi = row_lo + 8;
#pragma unroll
        for (int j = 0; j < 4; j++) {
            int col = cbase + j * 8 + (lane & 3) * 2;
            float2 lo = make_float2(acc[i][j][0], acc[i][j][1]);
            float2 hi = make_float2(acc[i][j][2], acc[i][j][3]);
            if (OPT & 64) {
                *(float2*)&C[czoff + (size_t)row_lo * N + col] = lo;
                *(float2*)&C[czoff + (size_t)row_hi * N + col] = hi;
                continue;
            }
            if (OPT & 1) {
                float2 bbv = *(const float2*)&bias[col];
                lo.x += bbv.x; lo.y += bbv.y;
                hi.x += bbv.x; hi.y += bbv.y;
            }
            if (OPT & 2) {
                lo.x = fmaxf(lo.x, 0.f); lo.y = fmaxf(lo.y, 0.f);
                hi.x = fmaxf(hi.x, 0.f); hi.y = fmaxf(hi.y, 0.f);
            }
            if (OPT & 32) {
                *(uint32_t*)&Ch[czoff + (size_t)row_lo * N + col] = packh2(lo.x, lo.y);
                *(uint32_t*)&Ch[czoff + (size_t)row_hi * N + col] = packh2(hi.x, hi.y);
            } else {
                *(float2*)&C[czoff + (size_t)row_lo * N + col] = lo;
                *(float2*)&C[czoff + (size_t)row_hi * N + col] = hi;
            }
        }
    }
}

// ---------------------------------------------------------------------------
// Reduce 2 split-K partials, /den, +x residual -> LN -> Hn (f32 + half)
// ---------------------------------------------------------------------------
__global__ void k_red_ln1(const float* __restrict__ x,
                          const float* __restrict__ gw, const float* __restrict__ bw) {
    __shared__ float red[8];
    int r = blockIdx.x;
    int b = r >> 11;
    int m = r & (CL - 1);
    int tid = threadIdx.x;
    size_t rowoff = (size_t)m * CD + tid;
    size_t zstride = (size_t)CL * CD;

    float v = g_part[((size_t)(b * 2 + 0)) * zstride + rowoff]
            + g_part[((size_t)(b * 2 + 1)) * zstride + rowoff];
    v = v / g_den[b * CL + m] + x[(size_t)r * CD + tid];

    float s = v;
    for (int o = 16; o > 0; o >>= 1) s += __shfl_xor_sync(0xffffffffu, s, o);
    if ((tid & 31) == 0) red[tid >> 5] = s;
    __syncthreads();
    if (tid < 32) {
        float rr = (tid < 8) ? red[tid] : 0.f;
        for (int o = 4; o > 0; o >>= 1) rr += __shfl_xor_sync(0xffffffffu, rr, o);
        if (tid == 0) red[0] = rr;
    }
    __syncthreads();
    float mu = red[0] * (1.f / CD);
    __syncthreads();
    float t = v - mu;
    float s2 = t * t;
    for (int o = 16; o > 0; o >>= 1) s2 += __shfl_xor_sync(0xffffffffu, s2, o);
    if ((tid & 31) == 0) red[tid >> 5] = s2;
    __syncthreads();
    if (tid < 32) {
        float rr = (tid < 8) ? red[tid] : 0.f;
        for (int o = 4; o > 0; o >>= 1) rr += __shfl_xor_sync(0xffffffffu, rr, o);
        if (tid == 0) red[0] = rr;
    }
    __syncthreads();
    float var = red[0] * (1.f / CD);
    float y = t * rsqrtf(var + 1e-5f) * gw[tid] + bw[tid];
    g_Hn[(size_t)r * CD + tid] = y;
    g_Hnh[(size_t)r * CD + tid] = __float2half_rn(y);
}

// ---------------------------------------------------------------------------
// Reduce 2 split-K partials + bias + residual(Hn) -> LN -> out
// ---------------------------------------------------------------------------
__global__ void k_red_ln2(const float* __restrict__ b2,
                          const float* __restrict__ gw, const float* __restrict__ bw,
                          float* __restrict__ out) {
    __shared__ float red[8];
    int r = blockIdx.x;
    int tid = threadIdx.x;
    size_t rowoff = (size_t)r * CD + tid;
    size_t zstride = (size_t)CB * CL * CD;

    float v = g_part[0 * zstride + rowoff] + g_part[1 * zstride + rowoff];
    v += b2[tid] + g_Hn[rowoff];

    float s = v;
    for (int o = 16; o > 0; o >>= 1) s += __shfl_xor_sync(0xffffffffu, s, o);
    if ((tid & 31) == 0) red[tid >> 5] = s;
    __syncthreads();
    if (tid < 32) {
        float rr = (tid < 8) ? red[tid] : 0.f;
        for (int o = 4; o > 0; o >>= 1) rr += __shfl_xor_sync(0xffffffffu, rr, o);
        if (tid == 0) red[0] = rr;
    }
    __syncthreads();
    float mu = red[0] * (1.f / CD);
    __syncthreads();
    float t = v - mu;
    float s2 = t * t;
    for (int o = 16; o > 0; o >>= 1) s2 += __shfl_xor_sync(0xffffffffu, s2, o);
    if ((tid & 31) == 0) red[tid >> 5] = s2;
    __syncthreads();
    if (tid < 32) {
        float rr = (tid < 8) ? red[tid] : 0.f;
        for (int o = 4; o > 0; o >>= 1) rr += __shfl_xor_sync(0xffffffffu, rr, o);
        if (tid == 0) red[0] = rr;
    }
    __syncthreads();
    float var = red[0] * (1.f / CD);
    out[rowoff] = t * rsqrtf(var + 1e-5f) * gw[tid] + bw[tid];
}

// ---------------------------------------------------------------------------
// kernel_launch
// ---------------------------------------------------------------------------
extern "C" void kernel_launch(void* const* d_in, const int* in_sizes, int n_in,
                              void* d_out, int out_size) {
    const float* x    = (const float*)d_in[0];
    const int*   mask = (const int*)  d_in[1];
    const float* W1   = (const float*)d_in[2];
    const float* b1   = (const float*)d_in[3];
    const float* W2   = (const float*)d_in[4];
    const float* b2   = (const float*)d_in[5];
    const float* g1   = (const float*)d_in[6];
    const float* be1  = (const float*)d_in[7];
    const float* g2   = (const float*)d_in[8];
    const float* be2  = (const float*)d_in[9];
    float* out = (float*)d_out;

    __half *pP, *pHnh, *pH1h, *pxh, *pW1h, *pW2h;
    float *pPart;
    cudaGetSymbolAddress((void**)&pP,    g_P);
    cudaGetSymbolAddress((void**)&pPart, g_part);
    cudaGetSymbolAddress((void**)&pHnh,  g_Hnh);
    cudaGetSymbolAddress((void**)&pH1h,  g_H1h);
    cudaGetSymbolAddress((void**)&pxh,   g_xh);
    cudaGetSymbolAddress((void**)&pW1h,  g_W1h);
    cudaGetSymbolAddress((void**)&pW2h,  g_W2h);

    const int DSMEM = 3 * 32768;
    cudaFuncSetAttribute(k_hgemm<64, 2>, cudaFuncAttributeMaxDynamicSharedMemorySize, DSMEM);
    cudaFuncSetAttribute(k_hgemm<35, 1>, cudaFuncAttributeMaxDynamicSharedMemorySize, DSMEM);

    // 1) token mean (half)
    k_mean<<<(CL * CDK + 255) / 256, 256>>>(x);
    // 2) zero denominators
    k_zero<<<CB * CL / 256, 256>>>();
    // 3) tensor-core scores + fused masked denominators
    k_scores_mma<<<dim3(CL / 128, CL / 128), 256>>>(mask);
    // 4) half conversions (mask folded into xh)
    k_xh<<<(CB * CL * CD / 16) / 256, 256>>>(x, mask);
    k_wh<<<(CD * CF / 16) / 256, 256>>>(W1, pW1h);
    k_wh<<<(CF * CD / 16) / 256, 256>>>(W2, pW2h);

    // 5) GEMM1 split-K2: part[b*2+s] = P[:, ks] @ xh_b[ks, :]  (raw partials)
    k_hgemm<64, 2><<<dim3(CD / 128, CL / 128, CB * 2), 256, DSMEM>>>(
        pP, pxh, nullptr, pPart, nullptr,
        CD, CL, (size_t)CL * CD, (size_t)CL * CD);

    // 6) reduce + /den + residual(x) + LN1 -> Hn, Hnh
    k_red_ln1<<<CB * CL, CD>>>(x, g1, be1);

    // 7) H1h = half(relu(Hn @ W1 + b1))   OPT = 1|2|32
    k_hgemm<35, 1><<<dim3(CF / 128, (CB * CL) / 128, 1), 256, DSMEM>>>(
        pHnh, pW1h, b1, nullptr, pH1h,
        CF, CD, 0, 0);

    // 8) GEMM3 split-K2: part[s] = H1h[:, ks] @ W2h[ks, :]  (raw partials)
    k_hgemm<64, 2><<<dim3(CD / 128, (CB * CL) / 128, 2), 256, DSMEM>>>(
        pH1h, pW2h, nullptr, pPart, nullptr,
        CD, CF, 0, (size_t)CB * CL * CD);

    // 9) reduce + bias + residual(Hn) + LN2 -> out
    k_red_ln2<<<CB * CL, CD>>>(b2, g2, be2, out);
}

// round 15
// speedup vs baseline: 4.7657x; 1.1768x over previous
#include <cuda_runtime.h>
#include <cuda_fp16.h>
#include <math.h>
#include <stdint.h>

// Problem constants (fixed by reference setup_inputs)
#define CB 4
#define CL 2048
#define CD 256
#define CH 8
#define CDK 32
#define CF 1024

// ---------------------------------------------------------------------------
// Scratch (device globals: allocation-free per harness rules)
// ---------------------------------------------------------------------------
__device__ __align__(16) __half g_mh[CL * CDK];                  // 128 KB
__device__ __align__(16) __half g_P[(size_t)CL * CL];            // 8 MB : exp(scores)
__device__ __align__(16) float  g_den[CB * CL];                  // 32 KB
__device__ __align__(16) float  g_part[(size_t)8 * CL * CD];     // 16 MB: split-K partials
__device__ __align__(16) float  g_Hn[(size_t)CB * CL * CD];      // 8 MB
__device__ __align__(16) __half g_Hnh[(size_t)CB * CL * CD];     // 4 MB
__device__ __align__(16) __half g_H1h[(size_t)CB * CL * CF];     // 16 MB
__device__ __align__(16) __half g_xh[(size_t)CB * CL * CD];      // 4 MB : masked x, half
__device__ __align__(16) __half g_W1h[(size_t)CD * CF];          // 512 KB
__device__ __align__(16) __half g_W2h[(size_t)CF * CD];          // 512 KB

__device__ __forceinline__ uint32_t packh2(float lo, float hi) {
    __half2 h = __floats2half2_rn(lo, hi);
    return *(uint32_t*)&h;
}

// ---------------------------------------------------------------------------
// mh[l, d] = half( mean over (b, h) of x[b, l, h*32 + d] ); also zeros g_den
// ---------------------------------------------------------------------------
__global__ void k_mean(const float* __restrict__ x) {
    int idx = blockIdx.x * blockDim.x + threadIdx.x;
    if (idx < CB * CL) g_den[idx] = 0.f;
    if (idx >= CL * CDK) return;
    int l = idx / CDK;
    int d = idx % CDK;
    float s = 0.f;
#pragma unroll
    for (int b = 0; b < CB; b++)
#pragma unroll
        for (int h = 0; h < CH; h++)
            s += x[((size_t)(b * CL) + l) * CD + h * CDK + d];
    g_mh[idx] = __float2half_rn(s * (1.f / 32.f));
}

// ---------------------------------------------------------------------------
// mma / ldmatrix / cp.async helpers
// ---------------------------------------------------------------------------
__device__ __forceinline__ void mma16816(float* d, const uint4& a, const uint2& b) {
    asm volatile(
        "mma.sync.aligned.m16n8k16.row.col.f32.f16.f16.f32 "
        "{%0,%1,%2,%3}, {%4,%5,%6,%7}, {%8,%9}, {%0,%1,%2,%3};"
        : "+f"(d[0]), "+f"(d[1]), "+f"(d[2]), "+f"(d[3])
        : "r"(a.x), "r"(a.y), "r"(a.z), "r"(a.w), "r"(b.x), "r"(b.y));
}
__device__ __forceinline__ void ldsm4(uint4& d, uint32_t a) {
    asm volatile("ldmatrix.sync.aligned.m8n8.x4.shared.b16 {%0,%1,%2,%3}, [%4];"
        : "=r"(d.x), "=r"(d.y), "=r"(d.z), "=r"(d.w) : "r"(a));
}
__device__ __forceinline__ void ldsm4t(uint32_t& r0, uint32_t& r1,
                                       uint32_t& r2, uint32_t& r3, uint32_t a) {
    asm volatile("ldmatrix.sync.aligned.m8n8.x4.trans.shared.b16 {%0,%1,%2,%3}, [%4];"
        : "=r"(r0), "=r"(r1), "=r"(r2), "=r"(r3) : "r"(a));
}
__device__ __forceinline__ void cpasync16(uint32_t s, const void* g) {
    asm volatile("cp.async.cg.shared.global [%0], [%1], 16;" :: "r"(s), "l"(g));
}
#define CP_COMMIT() asm volatile("cp.async.commit_group;" ::: "memory")
#define CP_WAIT1()  asm volatile("cp.async.wait_group 1;" ::: "memory")

// ---------------------------------------------------------------------------
// Tensor-core scores: P = exp(sin^2(clip(mh @ mh^T)/2)) (half) + fused
// masked row-sum denominators (atomicAdd into g_den).
// ---------------------------------------------------------------------------
__global__ void __launch_bounds__(256) k_scores_mma(const int* __restrict__ mask) {
    __shared__ __align__(16) __half sA[128 * 40];   // 80B row stride
    __shared__ __align__(16) __half sB[128 * 40];
    __shared__ float mk[CB][128];

    const int tid = threadIdx.x;
    const int lane = tid & 31;
    const int wid = tid >> 5;
    const int wr = wid >> 2;
    const int wc = wid & 3;
    const int i0 = blockIdx.y * 128;
    const int j0 = blockIdx.x * 128;

#pragma unroll
    for (int u = 0; u < 2; u++) {
        int cid = tid + u * 256;
        int r = cid >> 2, c = cid & 3;
        *(uint4*)&sA[r * 40 + c * 8] = *(const uint4*)&g_mh[(i0 + r) * CDK + c * 8];
        *(uint4*)&sB[r * 40 + c * 8] = *(const uint4*)&g_mh[(j0 + r) * CDK + c * 8];
    }
    {
        int b = tid >> 6, j = (tid & 63) * 2;
        mk[b][j]     = (mask[b * CL + j0 + j] != 0) ? 1.f : 0.f;
        mk[b][j + 1] = (mask[b * CL + j0 + j + 1] != 0) ? 1.f : 0.f;
    }
    __syncthreads();

    uint32_t aS = (uint32_t)__cvta_generic_to_shared(sA);
    uint32_t bS = (uint32_t)__cvta_generic_to_shared(sB);

    const int am8 = (lane & 7) + (((lane >> 3) & 1) << 3);
    const int kq  = lane >> 4;

    float acc[4][4][4];
#pragma unroll
    for (int i = 0; i < 4; i++)
#pragma unroll
        for (int j = 0; j < 4; j++)
#pragma unroll
            for (int q = 0; q < 4; q++) acc[i][j][q] = 0.f;

#pragma unroll
    for (int ks = 0; ks < 2; ks++) {
        uint4 af[4];
#pragma unroll
        for (int i = 0; i < 4; i++) {
            int m = wr * 64 + i * 16 + am8;
            ldsm4(af[i], aS + m * 80 + (ks * 2 + kq) * 16);
        }
        uint2 bf[4];
#pragma unroll
        for (int jj = 0; jj < 2; jj++) {
            int n = wc * 32 + jj * 16 + am8;
            uint4 t;
            ldsm4(t, bS + n * 80 + (ks * 2 + kq) * 16);
            bf[jj * 2]     = make_uint2(t.x, t.z);
            bf[jj * 2 + 1] = make_uint2(t.y, t.w);
        }
#pragma unroll
        for (int i = 0; i < 4; i++)
#pragma unroll
            for (int j = 0; j < 4; j++)
                mma16816(acc[i][j], af[i], bf[j]);
    }

    const float PI = 3.14159265358979323846f;
#pragma unroll
    for (int i = 0; i < 4; i++) {
        int row_lo = i0 + wr * 64 + i * 16 + (lane >> 2);
        int row_hi = row_lo + 8;
        float slo[CB] = {0.f, 0.f, 0.f, 0.f};
        float shi[CB] = {0.f, 0.f, 0.f, 0.f};
#pragma unroll
        for (int j = 0; j < 4; j++) {
            int cl = wc * 32 + j * 8 + (lane & 3) * 2;
            float p0 = __expf(0.5f * (1.f - __cosf(fminf(fmaxf(acc[i][j][0], -PI), PI))));
            float p1 = __expf(0.5f * (1.f - __cosf(fminf(fmaxf(acc[i][j][1], -PI), PI))));
            float p2 = __expf(0.5f * (1.f - __cosf(fminf(fmaxf(acc[i][j][2], -PI), PI))));
            float p3 = __expf(0.5f * (1.f - __cosf(fminf(fmaxf(acc[i][j][3], -PI), PI))));
            uint32_t wlo = packh2(p0, p1);
            uint32_t whi = packh2(p2, p3);
            *(uint32_t*)&g_P[(size_t)row_lo * CL + j0 + cl] = wlo;
            *(uint32_t*)&g_P[(size_t)row_hi * CL + j0 + cl] = whi;
            float2 flo = __half22float2(*(__half2*)&wlo);
            float2 fhi = __half22float2(*(__half2*)&whi);
#pragma unroll
            for (int b = 0; b < CB; b++) {
                slo[b] += flo.x * mk[b][cl] + flo.y * mk[b][cl + 1];
                shi[b] += fhi.x * mk[b][cl] + fhi.y * mk[b][cl + 1];
            }
        }
#pragma unroll
        for (int b = 0; b < CB; b++) {
            slo[b] += __shfl_xor_sync(0xffffffffu, slo[b], 1);
            slo[b] += __shfl_xor_sync(0xffffffffu, slo[b], 2);
            shi[b] += __shfl_xor_sync(0xffffffffu, shi[b], 1);
            shi[b] += __shfl_xor_sync(0xffffffffu, shi[b], 2);
        }
        if ((lane & 3) == 0) {
#pragma unroll
            for (int b = 0; b < CB; b++) {
                atomicAdd(&g_den[b * CL + row_lo], slo[b]);
                atomicAdd(&g_den[b * CL + row_hi], shi[b]);
            }
        }
    }
}

// ---------------------------------------------------------------------------
// Merged half conversions: blocks [0,1024) -> xh (masked), [1024,1152) -> W1h,
// [1152,1280) -> W2h. 8 elems / thread.
// ---------------------------------------------------------------------------
__global__ void k_convert(const float* __restrict__ x, const int* __restrict__ mask,
                          const float* __restrict__ W1, const float* __restrict__ W2) {
    int bid = blockIdx.x;
    if (bid < 1024) {
        size_t e = ((size_t)bid * 256 + threadIdx.x) * 8;
        int msk = mask[e >> 8];
        float4 v0 = *(const float4*)&x[e];
        float4 v1 = *(const float4*)&x[e + 4];
        if (!msk) {
            v0 = make_float4(0.f, 0.f, 0.f, 0.f);
            v1 = make_float4(0.f, 0.f, 0.f, 0.f);
        }
        uint4 o;
        o.x = packh2(v0.x, v0.y); o.y = packh2(v0.z, v0.w);
        o.z = packh2(v1.x, v1.y); o.w = packh2(v1.z, v1.w);
        *(uint4*)&g_xh[e] = o;
    } else {
        const float* src = (bid < 1152) ? W1 : W2;
        __half* dst = (bid < 1152) ? g_W1h : g_W2h;
        int lb = (bid < 1152) ? bid - 1024 : bid - 1152;
        size_t e = ((size_t)lb * 256 + threadIdx.x) * 8;
        float4 v0 = *(const float4*)&src[e];
        float4 v1 = *(const float4*)&src[e + 4];
        uint4 o;
        o.x = packh2(v0.x, v0.y); o.y = packh2(v0.z, v0.w);
        o.z = packh2(v1.x, v1.y); o.w = packh2(v1.z, v1.w);
        *(uint4*)&dst[e] = o;
    }
}

// ---------------------------------------------------------------------------
// FP16 tensor-core GEMM (cp.async 3-stage + ldmatrix)  [unchanged, known-good]
// OPT bits: 1=+bias, 2=relu, 32=half C out, 64=raw fp32 partial out
// ---------------------------------------------------------------------------
template <int OPT, int SPLIT>
__global__ void __launch_bounds__(256, 2) k_hgemm(
    const __half* __restrict__ A, const __half* __restrict__ B,
    const float* __restrict__ bias,
    float* __restrict__ C, __half* __restrict__ Ch,
    int N, int K, size_t sB, size_t sC)
{
    extern __shared__ __align__(128) char smem[];
    const int tid = threadIdx.x;
    const int lane = tid & 31;
    const int wid = tid >> 5;
    const int wr = wid >> 2;
    const int wc = wid & 3;

    const int z = blockIdx.z;
    const int bb = z / SPLIT;
    const int sp = z % SPLIT;
    const int kt = K / SPLIT;
    const int ksta = sp * kt;
    const size_t czoff = (size_t)z * sC;

    const int m0 = blockIdx.y * 128;
    const int n0 = blockIdx.x * 128;

    uint32_t sbase = (uint32_t)__cvta_generic_to_shared(smem);

    const __half* ag[4];
    const __half* bg[4];
    uint32_t asmo[4], bsmo[4];
#pragma unroll
    for (int i = 0; i < 4; i++) {
        int cid = tid + i * 256;
        int am = cid >> 3, kc = cid & 7;
        ag[i] = A + (size_t)(m0 + am) * K + ksta + kc * 8;
        asmo[i] = am * 128 + ((kc ^ (am & 7)) << 4);
        int bk = cid >> 4, bc = cid & 15;
        bg[i] = B + (size_t)bb * sB + (size_t)(ksta + bk) * N + n0 + bc * 8;
        bsmo[i] = 16384 + bk * 256 + (((bc & 8) | ((bc & 7) ^ (bk & 7))) << 4);
    }

    float acc[4][4][4];
#pragma unroll
    for (int i = 0; i < 4; i++)
#pragma unroll
        for (int j = 0; j < 4; j++)
#pragma unroll
            for (int q = 0; q < 4; q++) acc[i][j][q] = 0.f;

    const int NC = kt >> 6;

    {
        uint32_t sb = sbase;
#pragma unroll
        for (int i = 0; i < 4; i++) cpasync16(sb + asmo[i], ag[i]);
#pragma unroll
        for (int i = 0; i < 4; i++) cpasync16(sb + bsmo[i], bg[i]);
    }
    CP_COMMIT();
    {
        uint32_t sb = sbase + 32768;
#pragma unroll
        for (int i = 0; i < 4; i++) cpasync16(sb + asmo[i], ag[i] + 64);
#pragma unroll
        for (int i = 0; i < 4; i++) cpasync16(sb + bsmo[i], bg[i] + (size_t)64 * N);
    }
    CP_COMMIT();

    const int am8 = (lane & 7) + (((lane >> 3) & 1) << 3);
    const int kq  = lane >> 4;

    for (int c = 0; c < NC; c++) {
        CP_WAIT1();
        __syncthreads();
        if (c + 2 < NC) {
            uint32_t sb = sbase + ((c + 2) % 3) * 32768;
            const int ko = (c + 2) * 64;
#pragma unroll
            for (int i = 0; i < 4; i++) cpasync16(sb + asmo[i], ag[i] + ko);
#pragma unroll
            for (int i = 0; i < 4; i++) cpasync16(sb + bsmo[i], bg[i] + (size_t)ko * N);
        }
        CP_COMMIT();

        uint32_t abase = sbase + (c % 3) * 32768;
        uint32_t bbase = abase + 16384;
#pragma unroll
        for (int ks = 0; ks < 4; ks++) {
            uint4 af[4];
#pragma unroll
            for (int i = 0; i < 4; i++) {
                int m = wr * 64 + i * 16 + am8;
                uint32_t ad = abase + m * 128 + ((((ks * 2 + kq)) ^ (lane & 7)) << 4);
                ldsm4(af[i], ad);
            }
            uint2 bf[4];
#pragma unroll
            for (int jj = 0; jj < 2; jj++) {
                int k = ks * 16 + am8;
                int c2 = wc * 4 + jj * 2 + kq;
                uint32_t bd = bbase + k * 256 +
                              (((c2 & 8) | ((c2 & 7) ^ (lane & 7))) << 4);
                uint32_t r0, r1, r2, r3;
                ldsm4t(r0, r1, r2, r3, bd);
                bf[2 * jj]     = make_uint2(r0, r1);
                bf[2 * jj + 1] = make_uint2(r2, r3);
            }
#pragma unroll
            for (int i = 0; i < 4; i++)
#pragma unroll
                for (int j = 0; j < 4; j++)
                    mma16816(acc[i][j], af[i], bf[j]);
        }
    }

    const int rbase = m0 + wr * 64;
    const int cbase = n0 + wc * 32;
#pragma unroll
    for (int i = 0; i < 4; i++) {
        int row_lo = rbase + i * 16 + (lane >> 2);
        int row_hi = row_lo + 8;
#pragma unroll
        for (int j = 0; j < 4; j++) {
            int col = cbase + j * 8 + (lane & 3) * 2;
            float2 lo = make_float2(acc[i][j][0], acc[i][j][1]);
            float2 hi = make_float2(acc[i][j][2], acc[i][j][3]);
            if (OPT & 64) {
                *(float2*)&C[czoff + (size_t)row_lo * N + col] = lo;
                *(float2*)&C[czoff + (size_t)row_hi * N + col] = hi;
                continue;
            }
            if (OPT & 1) {
                float2 bbv = *(const float2*)&bias[col];
                lo.x += bbv.x; lo.y += bbv.y;
                hi.x += bbv.x; hi.y += bbv.y;
            }
            if (OPT & 2) {
                lo.x = fmaxf(lo.x, 0.f); lo.y = fmaxf(lo.y, 0.f);
                hi.x = fmaxf(hi.x, 0.f); hi.y = fmaxf(hi.y, 0.f);
            }
            if (OPT & 32) {
                *(uint32_t*)&Ch[czoff + (size_t)row_lo * N + col] = packh2(lo.x, lo.y);
                *(uint32_t*)&Ch[czoff + (size_t)row_hi * N + col] = packh2(hi.x, hi.y);
            } else {
                *(float2*)&C[czoff + (size_t)row_lo * N + col] = lo;
                *(float2*)&C[czoff + (size_t)row_hi * N + col] = hi;
            }
        }
    }
}

// ---------------------------------------------------------------------------
// Warp-per-row reduce+LN kernels: one warp handles one 256-wide row,
// 8 floats/lane, shfl-only reductions (no block barriers).
// ---------------------------------------------------------------------------
__device__ __forceinline__ float warp_sum(float v) {
#pragma unroll
    for (int o = 16; o > 0; o >>= 1) v += __shfl_xor_sync(0xffffffffu, v, o);
    return v;
}

// v = (part0+part1)/den + x  -> LN(g1,be1) -> Hn (f32) + Hnh (half)
__global__ void __launch_bounds__(256) k_red_ln1(
    const float* __restrict__ x,
    const float* __restrict__ gw, const float* __restrict__ bw) {
    int warp = threadIdx.x >> 5, lane = threadIdx.x & 31;
    int r = blockIdx.x * 8 + warp;            // 0..CB*CL-1
    int b = r >> 11, m = r & (CL - 1);
    size_t zs = (size_t)CL * CD;
    size_t po = (size_t)(b * 2) * zs + (size_t)m * CD + lane * 8;
    float4 a0 = *(const float4*)&g_part[po];
    float4 a1 = *(const float4*)&g_part[po + 4];
    float4 c0 = *(const float4*)&g_part[po + zs];
    float4 c1 = *(const float4*)&g_part[po + zs + 4];
    float invd = 1.f / g_den[b * CL + m];
    size_t xo = (size_t)r * CD + lane * 8;
    float4 x0 = *(const float4*)&x[xo];
    float4 x1 = *(const float4*)&x[xo + 4];

    float v[8];
    v[0] = (a0.x + c0.x) * invd + x0.x;
    v[1] = (a0.y + c0.y) * invd + x0.y;
    v[2] = (a0.z + c0.z) * invd + x0.z;
    v[3] = (a0.w + c0.w) * invd + x0.w;
    v[4] = (a1.x + c1.x) * invd + x1.x;
    v[5] = (a1.y + c1.y) * invd + x1.y;
    v[6] = (a1.z + c1.z) * invd + x1.z;
    v[7] = (a1.w + c1.w) * invd + x1.w;

    float s = 0.f;
#pragma unroll
    for (int i = 0; i < 8; i++) s += v[i];
    float mu = warp_sum(s) * (1.f / CD);
    float s2 = 0.f;
#pragma unroll
    for (int i = 0; i < 8; i++) {
        v[i] -= mu;
        s2 += v[i] * v[i];
    }
    float rstd = rsqrtf(warp_sum(s2) * (1.f / CD) + 1e-5f);

    float4 g0 = *(const float4*)&gw[lane * 8];
    float4 g1v = *(const float4*)&gw[lane * 8 + 4];
    float4 b0 = *(const float4*)&bw[lane * 8];
    float4 b1v = *(const float4*)&bw[lane * 8 + 4];
    float y[8];
    y[0] = v[0] * rstd * g0.x + b0.x;  y[1] = v[1] * rstd * g0.y + b0.y;
    y[2] = v[2] * rstd * g0.z + b0.z;  y[3] = v[3] * rstd * g0.w + b0.w;
    y[4] = v[4] * rstd * g1v.x + b1v.x; y[5] = v[5] * rstd * g1v.y + b1v.y;
    y[6] = v[6] * rstd * g1v.z + b1v.z; y[7] = v[7] * rstd * g1v.w + b1v.w;

    *(float4*)&g_Hn[xo]     = make_float4(y[0], y[1], y[2], y[3]);
    *(float4*)&g_Hn[xo + 4] = make_float4(y[4], y[5], y[6], y[7]);
    uint4 o;
    o.x = packh2(y[0], y[1]); o.y = packh2(y[2], y[3]);
    o.z = packh2(y[4], y[5]); o.w = packh2(y[6], y[7]);
    *(uint4*)&g_Hnh[xo] = o;
}

// v = part0+part1 + b2 + Hn -> LN(g2,be2) -> out
__global__ void __launch_bounds__(256) k_red_ln2(
    const float* __restrict__ b2,
    const float* __restrict__ gw, const float* __restrict__ bw,
    float* __restrict__ out) {
    int warp = threadIdx.x >> 5, lane = threadIdx.x & 31;
    int r = blockIdx.x * 8 + warp;
    size_t zs = (size_t)CB * CL * CD;
    size_t rowoff = (size_t)r * CD + lane * 8;
    float4 a0 = *(const float4*)&g_part[rowoff];
    float4 a1 = *(const float4*)&g_part[rowoff + 4];
    float4 c0 = *(const float4*)&g_part[rowoff + zs];
    float4 c1 = *(const float4*)&g_part[rowoff + zs + 4];
    float4 h0 = *(const float4*)&g_Hn[rowoff];
    float4 h1 = *(const float4*)&g_Hn[rowoff + 4];
    float4 bb0 = *(const float4*)&b2[lane * 8];
    float4 bb1 = *(const float4*)&b2[lane * 8 + 4];

    float v[8];
    v[0] = a0.x + c0.x + bb0.x + h0.x;
    v[1] = a0.y + c0.y + bb0.y + h0.y;
    v[2] = a0.z + c0.z + bb0.z + h0.z;
    v[3] = a0.w + c0.w + bb0.w + h0.w;
    v[4] = a1.x + c1.x + bb1.x + h1.x;
    v[5] = a1.y + c1.y + bb1.y + h1.y;
    v[6] = a1.z + c1.z + bb1.z + h1.z;
    v[7] = a1.w + c1.w + bb1.w + h1.w;

    float s = 0.f;
#pragma unroll
    for (int i = 0; i < 8; i++) s += v[i];
    float mu = warp_sum(s) * (1.f / CD);
    float s2 = 0.f;
#pragma unroll
    for (int i = 0; i < 8; i++) {
        v[i] -= mu;
        s2 += v[i] * v[i];
    }
    float rstd = rsqrtf(warp_sum(s2) * (1.f / CD) + 1e-5f);

    float4 g0 = *(const float4*)&gw[lane * 8];
    float4 g1v = *(const float4*)&gw[lane * 8 + 4];
    float4 w0 = *(const float4*)&bw[lane * 8];
    float4 w1 = *(const float4*)&bw[lane * 8 + 4];
    *(float4*)&out[rowoff] = make_float4(
        v[0] * rstd * g0.x + w0.x, v[1] * rstd * g0.y + w0.y,
        v[2] * rstd * g0.z + w0.z, v[3] * rstd * g0.w + w0.w);
    *(float4*)&out[rowoff + 4] = make_float4(
        v[4] * rstd * g1v.x + w1.x, v[5] * rstd * g1v.y + w1.y,
        v[6] * rstd * g1v.z + w1.z, v[7] * rstd * g1v.w + w1.w);
}

// ---------------------------------------------------------------------------
// kernel_launch
// ---------------------------------------------------------------------------
extern "C" void kernel_launch(void* const* d_in, const int* in_sizes, int n_in,
                              void* d_out, int out_size) {
    const float* x    = (const float*)d_in[0];
    const int*   mask = (const int*)  d_in[1];
    const float* W1   = (const float*)d_in[2];
    const float* b1   = (const float*)d_in[3];
    const float* W2   = (const float*)d_in[4];
    const float* b2   = (const float*)d_in[5];
    const float* g1   = (const float*)d_in[6];
    const float* be1  = (const float*)d_in[7];
    const float* g2   = (const float*)d_in[8];
    const float* be2  = (const float*)d_in[9];
    float* out = (float*)d_out;

    __half *pP, *pHnh, *pH1h, *pxh, *pW1h, *pW2h;
    float *pPart;
    cudaGetSymbolAddress((void**)&pP,    g_P);
    cudaGetSymbolAddress((void**)&pPart, g_part);
    cudaGetSymbolAddress((void**)&pHnh,  g_Hnh);
    cudaGetSymbolAddress((void**)&pH1h,  g_H1h);
    cudaGetSymbolAddress((void**)&pxh,   g_xh);
    cudaGetSymbolAddress((void**)&pW1h,  g_W1h);
    cudaGetSymbolAddress((void**)&pW2h,  g_W2h);

    const int DSMEM = 3 * 32768;
    cudaFuncSetAttribute(k_hgemm<64, 2>, cudaFuncAttributeMaxDynamicSharedMemorySize, DSMEM);
    cudaFuncSetAttribute(k_hgemm<35, 1>, cudaFuncAttributeMaxDynamicSharedMemorySize, DSMEM);

    // 1) token mean (half) + zero denominators
    k_mean<<<(CL * CDK + 255) / 256, 256>>>(x);
    // 2) tensor-core scores + fused masked denominators
    k_scores_mma<<<dim3(CL / 128, CL / 128), 256>>>(mask);
    // 3) merged half conversions (xh masked, W1h, W2h)
    k_convert<<<1280, 256>>>(x, mask, W1, W2);

    // 4) GEMM1 split-K2: part[b*2+s] = P[:, ks] @ xh_b[ks, :]  (raw partials)
    k_hgemm<64, 2><<<dim3(CD / 128, CL / 128, CB * 2), 256, DSMEM>>>(
        pP, pxh, nullptr, pPart, nullptr,
        CD, CL, (size_t)CL * CD, (size_t)CL * CD);

    // 5) reduce + /den + residual(x) + LN1 -> Hn, Hnh
    k_red_ln1<<<CB * CL / 8, 256>>>(x, g1, be1);

    // 6) H1h = half(relu(Hn @ W1 + b1))   OPT = 1|2|32
    k_hgemm<35, 1><<<dim3(CF / 128, (CB * CL) / 128, 1), 256, DSMEM>>>(
        pHnh, pW1h, b1, nullptr, pH1h,
        CF, CD, 0, 0);

    // 7) GEMM3 split-K2: part[s] = H1h[:, ks] @ W2h[ks, :]  (raw partials)
    k_hgemm<64, 2><<<dim3(CD / 128, (CB * CL) / 128, 2), 256, DSMEM>>>(
        pH1h, pW2h, nullptr, pPart, nullptr,
        CD, CF, 0, (size_t)CB * CL * CD);

    // 8) reduce + bias + residual(Hn) + LN2 -> out
    k_red_ln2<<<CB * CL / 8, 256>>>(b2, g2, be2, out);
}